// round 2
// baseline (speedup 1.0000x reference)
#include <cuda_runtime.h>
#include <math.h>

#define BB 64
#define LCC 1024
#define LQQ 128
#define DDIM 128
#define NSLICE 8

// Scratch (device globals, allocation-free)
__device__ float g_S[(size_t)BB * LCC * LQQ];         // 33.5 MB raw logits
__device__ float g_T[BB * LQQ * DDIM];                // final T
__device__ float g_Tpart[NSLICE][BB * LQQ * DDIM];    // split-K partials
__device__ float g_zpart[NSLICE][BB * LQQ];           // split-K colsum partials
__device__ float g_cw1[BB * LCC];
__device__ float g_qw2[BB * LQQ];

// ---------------------------------------------------------------------------
// K1: cw1[b,i] = c_rep[b,i,:]·w1 ; qw2[b,j] = q_rep[b,j,:]·w2  (warp per row)
// ---------------------------------------------------------------------------
__global__ __launch_bounds__(256) void k1_rank1(const float* __restrict__ c_rep,
                                                const float* __restrict__ q_rep,
                                                const float* __restrict__ w) {
    int gw   = (blockIdx.x * blockDim.x + threadIdx.x) >> 5;
    int lane = threadIdx.x & 31;
    const int NC = BB * LCC;
    if (gw < NC) {
        const float* row = c_rep + (size_t)gw * DDIM;
        float s = 0.f;
#pragma unroll
        for (int k = 0; k < 4; k++) s = fmaf(row[lane + 32 * k], w[lane + 32 * k], s);
#pragma unroll
        for (int o = 16; o > 0; o >>= 1) s += __shfl_xor_sync(0xffffffffu, s, o);
        if (lane == 0) g_cw1[gw] = s;
    } else if (gw < NC + BB * LQQ) {
        int r = gw - NC;
        const float* row = q_rep + (size_t)r * DDIM;
        float s = 0.f;
#pragma unroll
        for (int k = 0; k < 4; k++) s = fmaf(row[lane + 32 * k], w[DDIM + lane + 32 * k], s);
#pragma unroll
        for (int o = 16; o > 0; o >>= 1) s += __shfl_xor_sync(0xffffffffu, s, o);
        if (lane == 0) g_qw2[r] = s;
    }
}

// ---------------------------------------------------------------------------
// K2: S[b,i,j] = cw1 + qw2 + sum_d (c[i,d]*w3[d]) * q[j,d]
// Block: 64 i x 128 j, K=128.  Thread: 4i x 8j register tile.
// ---------------------------------------------------------------------------
__global__ __launch_bounds__(256) void k2_S(const float* __restrict__ c_rep,
                                            const float* __restrict__ q_rep,
                                            const float* __restrict__ w) {
    int b  = blockIdx.y;
    int i0 = blockIdx.x * 64;
    __shared__ float cs[32][68];    // [k][i]  (c * w3), transposed
    __shared__ float qs[32][132];   // [k][j]  transposed
    int t  = threadIdx.x;
    int tx = t & 15;     // j-group (8 j)
    int ty = t >> 4;     // i-group (4 i)
    float acc[4][8];
#pragma unroll
    for (int a = 0; a < 4; a++)
#pragma unroll
        for (int c = 0; c < 8; c++) acc[a][c] = 0.f;

    const float* cb = c_rep + ((size_t)b * LCC + i0) * DDIM;
    const float* qb = q_rep + (size_t)b * LQQ * DDIM;
    const float* w3 = w + 2 * DDIM;

    for (int k0 = 0; k0 < DDIM; k0 += 32) {
#pragma unroll
        for (int l = 0; l < 2; l++) {                 // c tile: 64x32, transpose+scale
            int idx = t + l * 256;
            int i   = idx >> 3;
            int kq  = idx & 7;
            float4 v = *(const float4*)(cb + (size_t)i * DDIM + k0 + kq * 4);
            int kk = kq * 4;
            cs[kk + 0][i] = v.x * w3[k0 + kk + 0];
            cs[kk + 1][i] = v.y * w3[k0 + kk + 1];
            cs[kk + 2][i] = v.z * w3[k0 + kk + 2];
            cs[kk + 3][i] = v.w * w3[k0 + kk + 3];
        }
#pragma unroll
        for (int l = 0; l < 4; l++) {                 // q tile: 128x32, transpose
            int idx = t + l * 256;
            int j   = idx >> 3;
            int kq  = idx & 7;
            float4 v = *(const float4*)(qb + (size_t)j * DDIM + k0 + kq * 4);
            int kk = kq * 4;
            qs[kk + 0][j] = v.x; qs[kk + 1][j] = v.y;
            qs[kk + 2][j] = v.z; qs[kk + 3][j] = v.w;
        }
        __syncthreads();
#pragma unroll
        for (int k = 0; k < 32; k++) {
            float af[4], bf[8];
#pragma unroll
            for (int a = 0; a < 4; a++) af[a] = cs[k][ty * 4 + a];
#pragma unroll
            for (int c = 0; c < 8; c++) bf[c] = qs[k][tx * 8 + c];
#pragma unroll
            for (int a = 0; a < 4; a++)
#pragma unroll
                for (int c = 0; c < 8; c++)
                    acc[a][c] = fmaf(af[a], bf[c], acc[a][c]);
        }
        __syncthreads();
    }
    float qwf[8];
#pragma unroll
    for (int c = 0; c < 8; c++) qwf[c] = g_qw2[b * LQQ + tx * 8 + c];
#pragma unroll
    for (int a = 0; a < 4; a++) {
        int i = ty * 4 + a;
        float cw = g_cw1[b * LCC + i0 + i];
        float* o = g_S + ((size_t)b * LCC + i0 + i) * LQQ + tx * 8;
        float4 v0 = make_float4(acc[a][0] + cw + qwf[0], acc[a][1] + cw + qwf[1],
                                acc[a][2] + cw + qwf[2], acc[a][3] + cw + qwf[3]);
        float4 v1 = make_float4(acc[a][4] + cw + qwf[4], acc[a][5] + cw + qwf[5],
                                acc[a][6] + cw + qwf[6], acc[a][7] + cw + qwf[7]);
        *(float4*)o       = v0;
        *(float4*)(o + 4) = v1;
    }
}

// ---------------------------------------------------------------------------
// K3: split-K partials of T numerator and column softmax denominator.
//   E[k,j] = c_mask[k] ? 0 : exp(S[k,j])   (no max needed: |S| <~ 7)
//   Tpart[slice][j,d] = sum_{k in slice} E[k,j] * c[k,d]
//   zpart[slice][j]   = sum_{k in slice} E[k,j]
// Block: slice of 128 k rows; 128 j x 128 d; thread: 8j x 8d tile.
// ---------------------------------------------------------------------------
__global__ __launch_bounds__(256) void k3_Tpart(const float* __restrict__ c_rep,
                                                const int* __restrict__ c_mask) {
    int b     = blockIdx.y;
    int slice = blockIdx.x;
    int kbase = slice * 128;
    __shared__ float es[32][132];   // exp(S) [k][j]
    __shared__ float cs[32][132];   // c_rep  [k][d]
    int t  = threadIdx.x;
    int tx = t & 15;   // d-group (8 d)
    int ty = t >> 4;   // j-group (8 j)
    float acc[8][8];
    float zacc[8];
#pragma unroll
    for (int jj = 0; jj < 8; jj++) {
        zacc[jj] = 0.f;
#pragma unroll
        for (int dd = 0; dd < 8; dd++) acc[jj][dd] = 0.f;
    }

    for (int k0 = 0; k0 < 128; k0 += 32) {
#pragma unroll
        for (int l = 0; l < 4; l++) {
            int idx = t + l * 256;
            int kk  = idx >> 5;
            int jq  = idx & 31;
            int krow = kbase + k0 + kk;
            float4 v = *(const float4*)(g_S + ((size_t)b * LCC + krow) * LQQ + jq * 4);
            float m = c_mask[b * LCC + krow] ? 0.f : 1.f;
            es[kk][jq * 4 + 0] = m * expf(v.x);
            es[kk][jq * 4 + 1] = m * expf(v.y);
            es[kk][jq * 4 + 2] = m * expf(v.z);
            es[kk][jq * 4 + 3] = m * expf(v.w);
        }
#pragma unroll
        for (int l = 0; l < 4; l++) {
            int idx = t + l * 256;
            int kk  = idx >> 5;
            int dq  = idx & 31;
            int krow = kbase + k0 + kk;
            float4 v = *(const float4*)(c_rep + ((size_t)b * LCC + krow) * DDIM + dq * 4);
            cs[kk][dq * 4 + 0] = v.x; cs[kk][dq * 4 + 1] = v.y;
            cs[kk][dq * 4 + 2] = v.z; cs[kk][dq * 4 + 3] = v.w;
        }
        __syncthreads();
#pragma unroll
        for (int k = 0; k < 32; k++) {
            float ef[8], cf[8];
#pragma unroll
            for (int jj = 0; jj < 8; jj++) ef[jj] = es[k][ty * 8 + jj];
#pragma unroll
            for (int dd = 0; dd < 8; dd++) cf[dd] = cs[k][tx * 8 + dd];
#pragma unroll
            for (int jj = 0; jj < 8; jj++) zacc[jj] += ef[jj];
#pragma unroll
            for (int jj = 0; jj < 8; jj++)
#pragma unroll
                for (int dd = 0; dd < 8; dd++)
                    acc[jj][dd] = fmaf(ef[jj], cf[dd], acc[jj][dd]);
        }
        __syncthreads();
    }
#pragma unroll
    for (int jj = 0; jj < 8; jj++) {
        int j = ty * 8 + jj;
        float* dst = &g_Tpart[slice][((size_t)(b * LQQ + j)) * DDIM + tx * 8];
        *(float4*)dst       = make_float4(acc[jj][0], acc[jj][1], acc[jj][2], acc[jj][3]);
        *(float4*)(dst + 4) = make_float4(acc[jj][4], acc[jj][5], acc[jj][6], acc[jj][7]);
    }
    if (tx == 0) {
#pragma unroll
        for (int jj = 0; jj < 8; jj++)
            g_zpart[slice][b * LQQ + ty * 8 + jj] = zacc[jj];
    }
}

// ---------------------------------------------------------------------------
// K3r: reduce split-K partials -> T[b,j,d] = (sum_s num) / (sum_s z)
// ---------------------------------------------------------------------------
__global__ __launch_bounds__(256) void k3_reduce() {
    int idx = blockIdx.x * 256 + threadIdx.x;        // B*LQ*D = 1,048,576
    if (idx < BB * LQQ * DDIM) {
        int bj = idx / DDIM;
        float num = 0.f, z = 0.f;
#pragma unroll
        for (int s = 0; s < NSLICE; s++) num += g_Tpart[s][idx];
#pragma unroll
        for (int s = 0; s < NSLICE; s++) z += g_zpart[s][bj];
        g_T[idx] = num / z;
    }
}

// ---------------------------------------------------------------------------
// K4: row softmax S1, then fused dual-GEMM A = S1*q, Batt = S1*T, and output
// concat [c, A, c*A, c*Batt].  Block: 64 i rows; thread tile: 4i x 8d (x2).
// ---------------------------------------------------------------------------
__global__ __launch_bounds__(256) void k4_out(const float* __restrict__ c_rep,
                                              const float* __restrict__ q_rep,
                                              const int* __restrict__ q_mask,
                                              float* __restrict__ out) {
    int b  = blockIdx.y;
    int i0 = blockIdx.x * 64;
    extern __shared__ float sm[];
    float* ps = sm;                   // [128 j][68 i]  exp values (transposed)
    float* qs = sm + 128 * 68;        // [32 j][132 d]  chunk
    float* ts = qs + 32 * 132;        // [32 j][132 d]  chunk
    __shared__ float qmf[128];
    __shared__ float zp[64][4];
    __shared__ float zrow[64];
    int t = threadIdx.x;
    if (t < 128) qmf[t] = q_mask[b * LQQ + t] ? 0.f : 1.f;
    __syncthreads();

    // phase A: load S rows, mask+exp, transpose into ps, row sums
    {
        int i  = t >> 2;              // 0..63
        int q4 = t & 3;
        const float4* srow = (const float4*)(g_S + ((size_t)(b * LCC + i0 + i)) * LQQ);
        float part = 0.f;
#pragma unroll
        for (int l = 0; l < 8; l++) {
            int f = q4 + l * 4;       // float4 index 0..31 (coalesced across quad)
            float4 v = srow[f];
            int j = f * 4;
            float e0 = qmf[j + 0] * expf(v.x);
            float e1 = qmf[j + 1] * expf(v.y);
            float e2 = qmf[j + 2] * expf(v.z);
            float e3 = qmf[j + 3] * expf(v.w);
            ps[(j + 0) * 68 + i] = e0;
            ps[(j + 1) * 68 + i] = e1;
            ps[(j + 2) * 68 + i] = e2;
            ps[(j + 3) * 68 + i] = e3;
            part += e0 + e1 + e2 + e3;
        }
        zp[i][q4] = part;
    }
    __syncthreads();
    if (t < 64) zrow[t] = 1.f / (zp[t][0] + zp[t][1] + zp[t][2] + zp[t][3]);

    int tx = t & 15, ty = t >> 4;
    float accA[4][8], accB[4][8];
#pragma unroll
    for (int a = 0; a < 4; a++)
#pragma unroll
        for (int c = 0; c < 8; c++) { accA[a][c] = 0.f; accB[a][c] = 0.f; }

    for (int j0 = 0; j0 < 128; j0 += 32) {
        __syncthreads();   // protect qs/ts from previous iteration's readers (and order zrow)
#pragma unroll
        for (int l = 0; l < 4; l++) {
            int idx = t + l * 256;
            int jj  = idx >> 5;
            int dq  = idx & 31;
            float4 v = *(const float4*)(q_rep + ((size_t)(b * LQQ + j0 + jj)) * DDIM + dq * 4);
            *(float4*)(qs + jj * 132 + dq * 4) = v;
            float4 u = *(const float4*)(g_T + ((size_t)(b * LQQ + j0 + jj)) * DDIM + dq * 4);
            *(float4*)(ts + jj * 132 + dq * 4) = u;
        }
        __syncthreads();
#pragma unroll
        for (int k = 0; k < 32; k++) {
            float pf[4], qf[8], tf[8];
#pragma unroll
            for (int a = 0; a < 4; a++) pf[a] = ps[(j0 + k) * 68 + ty * 4 + a];
#pragma unroll
            for (int c = 0; c < 8; c++) qf[c] = qs[k * 132 + tx * 8 + c];
#pragma unroll
            for (int c = 0; c < 8; c++) tf[c] = ts[k * 132 + tx * 8 + c];
#pragma unroll
            for (int a = 0; a < 4; a++)
#pragma unroll
                for (int c = 0; c < 8; c++) {
                    accA[a][c] = fmaf(pf[a], qf[c], accA[a][c]);
                    accB[a][c] = fmaf(pf[a], tf[c], accB[a][c]);
                }
        }
    }
    __syncthreads();

    // epilogue: out[b,i, 0:128]=c ; [128:256]=A ; [256:384]=c*A ; [384:512]=c*Batt
#pragma unroll
    for (int a = 0; a < 4; a++) {
        int i = ty * 4 + a;
        float zi = zrow[i];
        const float* crow = c_rep + ((size_t)(b * LCC + i0 + i)) * DDIM + tx * 8;
        float4 c0 = *(const float4*)crow;
        float4 c1 = *(const float4*)(crow + 4);
        float cv[8] = {c0.x, c0.y, c0.z, c0.w, c1.x, c1.y, c1.z, c1.w};
        float av[8], bv[8];
#pragma unroll
        for (int c = 0; c < 8; c++) { av[c] = accA[a][c] * zi; bv[c] = accB[a][c] * zi; }
        float* ob = out + ((size_t)(b * LCC + i0 + i)) * (4 * DDIM);
        *(float4*)(ob + tx * 8)               = c0;
        *(float4*)(ob + tx * 8 + 4)           = c1;
        *(float4*)(ob + DDIM + tx * 8)        = make_float4(av[0], av[1], av[2], av[3]);
        *(float4*)(ob + DDIM + tx * 8 + 4)    = make_float4(av[4], av[5], av[6], av[7]);
        *(float4*)(ob + 2 * DDIM + tx * 8)    = make_float4(cv[0] * av[0], cv[1] * av[1], cv[2] * av[2], cv[3] * av[3]);
        *(float4*)(ob + 2 * DDIM + tx * 8 + 4) = make_float4(cv[4] * av[4], cv[5] * av[5], cv[6] * av[6], cv[7] * av[7]);
        *(float4*)(ob + 3 * DDIM + tx * 8)    = make_float4(cv[0] * bv[0], cv[1] * bv[1], cv[2] * bv[2], cv[3] * bv[3]);
        *(float4*)(ob + 3 * DDIM + tx * 8 + 4) = make_float4(cv[4] * bv[4], cv[5] * bv[5], cv[6] * bv[6], cv[7] * bv[7]);
    }
}

// ---------------------------------------------------------------------------
extern "C" void kernel_launch(void* const* d_in, const int* in_sizes, int n_in,
                              void* d_out, int out_size) {
    const float* c_rep  = (const float*)d_in[0];
    const float* q_rep  = (const float*)d_in[1];
    const int*   c_mask = (const int*)d_in[2];
    const int*   q_mask = (const int*)d_in[3];
    const float* w      = (const float*)d_in[4];
    float* out = (float*)d_out;

    // K1: rank-1 projections
    {
        int total_warps = BB * LCC + BB * LQQ;       // 73728
        int blocks = total_warps / 8;                // 256 threads = 8 warps
        k1_rank1<<<blocks, 256>>>(c_rep, q_rep, w);
    }
    // K2: logits S
    {
        dim3 g(LCC / 64, BB);
        k2_S<<<g, 256>>>(c_rep, q_rep, w);
    }
    // K3: T partials (split-K over LC) + column softmax denominators
    {
        dim3 g(NSLICE, BB);
        k3_Tpart<<<g, 256>>>(c_rep, c_mask);
    }
    // K3r: reduce
    k3_reduce<<<(BB * LQQ * DDIM) / 256, 256>>>();
    // K4: row softmax + dual GEMM + output assembly
    {
        int smem = (128 * 68 + 32 * 132 + 32 * 132) * 4;  // 68608 B
        cudaFuncSetAttribute(k4_out, cudaFuncAttributeMaxDynamicSharedMemorySize, smem);
        dim3 g(LCC / 64, BB);
        k4_out<<<g, 256, smem>>>(c_rep, q_rep, q_mask, out);
    }
}

// round 3
// speedup vs baseline: 3.4187x; 3.4187x over previous
#include <cuda_runtime.h>
#include <cuda_fp16.h>
#include <math.h>

#define BB 64
#define LCC 1024
#define LQQ 128
#define DDIM 128
#define NSL 4          // K3 split-K slices
#define LDH 136        // smem row stride in halfs (272B: 16B-aligned, conflict-free ldsm)

// ---- device scratch (allocation-free) ----
__device__ __half g_cwh[(size_t)BB * LCC * DDIM];  // fp16(c * w3)
__device__ __half g_ch [(size_t)BB * LCC * DDIM];  // fp16(c * cmf)
__device__ __half g_qh [BB * LQQ * DDIM];          // fp16(q)
__device__ __half g_qmh[BB * LQQ * DDIM];          // fp16(q * qmf)
__device__ __half g_Eh [(size_t)BB * LCC * LQQ];   // fp16(exp(S))
__device__ __half g_Tm [BB * LQQ * DDIM];          // fp16(T * qmf)
__device__ float  g_Tp [NSL][BB * LQQ * DDIM];     // T numerator partials
__device__ float  g_cw1[BB * LCC];
__device__ float  g_qw2[BB * LQQ];
__device__ float  g_z1inv[BB * LCC];
__device__ float  g_z2p[8][BB * LQQ];              // col-sum partials per i-tile

// ---- mma / ldmatrix helpers ----
__device__ __forceinline__ unsigned sm_addr(const void* p) {
    return (unsigned)__cvta_generic_to_shared(p);
}
__device__ __forceinline__ void ldsm_x4(unsigned a, unsigned& r0, unsigned& r1,
                                        unsigned& r2, unsigned& r3) {
    asm volatile("ldmatrix.sync.aligned.m8n8.x4.shared.b16 {%0,%1,%2,%3}, [%4];"
                 : "=r"(r0), "=r"(r1), "=r"(r2), "=r"(r3) : "r"(a));
}
__device__ __forceinline__ void ldsm_x4t(unsigned a, unsigned& r0, unsigned& r1,
                                         unsigned& r2, unsigned& r3) {
    asm volatile("ldmatrix.sync.aligned.m8n8.x4.trans.shared.b16 {%0,%1,%2,%3}, [%4];"
                 : "=r"(r0), "=r"(r1), "=r"(r2), "=r"(r3) : "r"(a));
}
__device__ __forceinline__ void mma16816(float& c0, float& c1, float& c2, float& c3,
                                         unsigned a0, unsigned a1, unsigned a2, unsigned a3,
                                         unsigned b0, unsigned b1) {
    asm volatile(
        "mma.sync.aligned.m16n8k16.row.col.f32.f16.f16.f32 "
        "{%0,%1,%2,%3}, {%4,%5,%6,%7}, {%8,%9}, {%0,%1,%2,%3};"
        : "+f"(c0), "+f"(c1), "+f"(c2), "+f"(c3)
        : "r"(a0), "r"(a1), "r"(a2), "r"(a3), "r"(b0), "r"(b1));
}

// ---------------------------------------------------------------------------
// K0: per-row prep. Warp per row. Computes cw1/qw2 (fp32 dot), converts
// operands to fp16 with masks/w3 folded in.
// ---------------------------------------------------------------------------
__global__ __launch_bounds__(256) void k0_prep(const float* __restrict__ c_rep,
                                               const float* __restrict__ q_rep,
                                               const int* __restrict__ c_mask,
                                               const int* __restrict__ q_mask,
                                               const float* __restrict__ w) {
    int gw   = (blockIdx.x * 256 + threadIdx.x) >> 5;
    int lane = threadIdx.x & 31;
    const int NC = BB * LCC;
    if (gw < NC) {
        float4 cv = *(const float4*)(c_rep + (size_t)gw * DDIM + lane * 4);
        float4 w1 = *(const float4*)(w + lane * 4);
        float4 w3 = *(const float4*)(w + 2 * DDIM + lane * 4);
        float s = cv.x * w1.x + cv.y * w1.y + cv.z * w1.z + cv.w * w1.w;
#pragma unroll
        for (int o = 16; o > 0; o >>= 1) s += __shfl_xor_sync(~0u, s, o);
        if (lane == 0) g_cw1[gw] = s;
        float mf = c_mask[gw] ? 0.f : 1.f;
        __half2 a0 = __floats2half2_rn(cv.x * w3.x, cv.y * w3.y);
        __half2 a1 = __floats2half2_rn(cv.z * w3.z, cv.w * w3.w);
        uint2 u; u.x = *(unsigned*)&a0; u.y = *(unsigned*)&a1;
        *(uint2*)(g_cwh + (size_t)gw * DDIM + lane * 4) = u;
        __half2 m0 = __floats2half2_rn(cv.x * mf, cv.y * mf);
        __half2 m1 = __floats2half2_rn(cv.z * mf, cv.w * mf);
        uint2 v; v.x = *(unsigned*)&m0; v.y = *(unsigned*)&m1;
        *(uint2*)(g_ch + (size_t)gw * DDIM + lane * 4) = v;
    } else if (gw < NC + BB * LQQ) {
        int r = gw - NC;
        float4 qv = *(const float4*)(q_rep + (size_t)r * DDIM + lane * 4);
        float4 w2 = *(const float4*)(w + DDIM + lane * 4);
        float s = qv.x * w2.x + qv.y * w2.y + qv.z * w2.z + qv.w * w2.w;
#pragma unroll
        for (int o = 16; o > 0; o >>= 1) s += __shfl_xor_sync(~0u, s, o);
        if (lane == 0) g_qw2[r] = s;
        float mf = q_mask[r] ? 0.f : 1.f;
        __half2 a0 = __floats2half2_rn(qv.x, qv.y);
        __half2 a1 = __floats2half2_rn(qv.z, qv.w);
        uint2 u; u.x = *(unsigned*)&a0; u.y = *(unsigned*)&a1;
        *(uint2*)(g_qh + (size_t)r * DDIM + lane * 4) = u;
        __half2 m0 = __floats2half2_rn(qv.x * mf, qv.y * mf);
        __half2 m1 = __floats2half2_rn(qv.z * mf, qv.w * mf);
        uint2 v; v.x = *(unsigned*)&m0; v.y = *(unsigned*)&m1;
        *(uint2*)(g_qmh + (size_t)r * DDIM + lane * 4) = v;
    }
}

// ---------------------------------------------------------------------------
// K2: S = cw1 + qw2 + cwh·qh^T  (M=128 i, N=128 j, K=128 d), then E=exp(S)
// stored fp16, z1 (row sums, qmf-masked) finalized, z2 partials (col sums,
// cmf-masked) staged. Warps 4(m)x2(n), warp tile 32x64.
// ---------------------------------------------------------------------------
__global__ __launch_bounds__(256) void k2_SE(const int* __restrict__ c_mask,
                                             const int* __restrict__ q_mask) {
    int b = blockIdx.y, i0 = blockIdx.x * 128;
    extern __shared__ __half sm2[];
    __half* cw_s = sm2;                // [128][LDH]  A: rows i, cols d
    __half* q_s  = sm2 + 128 * LDH;    // [128][LDH]  B: rows j, cols d
    __shared__ float z1s[128][2];
    __shared__ float z2s[128][4];
    __shared__ float qmf_s[128], cmf_s[128];
    int t = threadIdx.x, lane = t & 31, wp = t >> 5, wm = wp >> 1, wn = wp & 1;
    if (t < 128) {
        qmf_s[t] = q_mask[b * LQQ + t] ? 0.f : 1.f;
        cmf_s[t] = c_mask[b * LCC + i0 + t] ? 0.f : 1.f;
    }
    const uint4* gc = (const uint4*)(g_cwh + ((size_t)(b * LCC + i0)) * DDIM);
    const uint4* gq = (const uint4*)(g_qh + (size_t)b * LQQ * DDIM);
#pragma unroll
    for (int l = 0; l < 8; l++) {
        int u = t + l * 256, row = u >> 4, c16 = u & 15;
        *(uint4*)&cw_s[row * LDH + c16 * 8] = gc[u];
        *(uint4*)&q_s [row * LDH + c16 * 8] = gq[u];
    }
    __syncthreads();

    float acc[2][8][4];
#pragma unroll
    for (int a = 0; a < 2; a++)
#pragma unroll
        for (int c = 0; c < 8; c++)
#pragma unroll
            for (int k = 0; k < 4; k++) acc[a][c][k] = 0.f;

    unsigned aB = sm_addr(&cw_s[(wm * 32 + (lane & 15)) * LDH + 8 * (lane >> 4)]);
    unsigned bB = sm_addr(&q_s[(wn * 64 + 8 * ((lane >> 4) & 1) + (lane & 7)) * LDH
                               + 8 * ((lane >> 3) & 1)]);
#pragma unroll
    for (int ks = 0; ks < 8; ks++) {
        unsigned A[2][4];
        ldsm_x4(aB + ks * 32,                 A[0][0], A[0][1], A[0][2], A[0][3]);
        ldsm_x4(aB + 16 * LDH * 2 + ks * 32,  A[1][0], A[1][1], A[1][2], A[1][3]);
        unsigned Bf[8][2];
#pragma unroll
        for (int np = 0; np < 4; np++) {
            unsigned r0, r1, r2, r3;
            ldsm_x4(bB + np * (16 * LDH * 2) + ks * 32, r0, r1, r2, r3);
            Bf[2 * np][0] = r0; Bf[2 * np][1] = r1;
            Bf[2 * np + 1][0] = r2; Bf[2 * np + 1][1] = r3;
        }
#pragma unroll
        for (int a = 0; a < 2; a++)
#pragma unroll
            for (int c = 0; c < 8; c++)
                mma16816(acc[a][c][0], acc[a][c][1], acc[a][c][2], acc[a][c][3],
                         A[a][0], A[a][1], A[a][2], A[a][3], Bf[c][0], Bf[c][1]);
    }

    // epilogue: add rank-1 terms, exp, store E, accumulate z1/z2
    int g = lane >> 2, q4 = lane & 3;
    float z1a[2][2] = {{0.f, 0.f}, {0.f, 0.f}};
    float z2a[8][2];
#pragma unroll
    for (int c = 0; c < 8; c++) { z2a[c][0] = 0.f; z2a[c][1] = 0.f; }
#pragma unroll
    for (int a = 0; a < 2; a++) {
        int lr0 = wm * 32 + a * 16 + g;
        float cwv0 = g_cw1[b * LCC + i0 + lr0];
        float cwv1 = g_cw1[b * LCC + i0 + lr0 + 8];
        float cmf0 = cmf_s[lr0], cmf1 = cmf_s[lr0 + 8];
        __half* e0p = g_Eh + ((size_t)(b * LCC + i0 + lr0)) * LQQ;
        __half* e1p = e0p + 8 * LQQ;
#pragma unroll
        for (int c = 0; c < 8; c++) {
            int col = wn * 64 + c * 8 + 2 * q4;
            float qw0 = g_qw2[b * LQQ + col], qw1 = g_qw2[b * LQQ + col + 1];
            float qf0 = qmf_s[col], qf1 = qmf_s[col + 1];
            float s0 = acc[a][c][0] + cwv0 + qw0;
            float s1 = acc[a][c][1] + cwv0 + qw1;
            float s2 = acc[a][c][2] + cwv1 + qw0;
            float s3 = acc[a][c][3] + cwv1 + qw1;
            __half h0 = __float2half(__expf(s0));
            __half h1 = __float2half(__expf(s1));
            __half h2 = __float2half(__expf(s2));
            __half h3 = __float2half(__expf(s3));
            *(__half2*)(e0p + col) = __halves2half2(h0, h1);
            *(__half2*)(e1p + col) = __halves2half2(h2, h3);
            float e0 = __half2float(h0), e1 = __half2float(h1);
            float e2 = __half2float(h2), e3 = __half2float(h3);
            z1a[a][0] += qf0 * e0 + qf1 * e1;
            z1a[a][1] += qf0 * e2 + qf1 * e3;
            z2a[c][0] += cmf0 * e0 + cmf1 * e2;
            z2a[c][1] += cmf0 * e1 + cmf1 * e3;
        }
    }
#pragma unroll
    for (int a = 0; a < 2; a++)
#pragma unroll
        for (int h = 0; h < 2; h++) {
            float v = z1a[a][h];
            v += __shfl_xor_sync(~0u, v, 1);
            v += __shfl_xor_sync(~0u, v, 2);
            if (q4 == 0) z1s[wm * 32 + a * 16 + g + 8 * h][wn] = v;
        }
#pragma unroll
    for (int c = 0; c < 8; c++)
#pragma unroll
        for (int s = 0; s < 2; s++) {
            float v = z2a[c][s];
            v += __shfl_xor_sync(~0u, v, 4);
            v += __shfl_xor_sync(~0u, v, 8);
            v += __shfl_xor_sync(~0u, v, 16);
            if (g == 0) z2s[wn * 64 + c * 8 + 2 * q4 + s][wm] = v;
        }
    __syncthreads();
    if (t < 128) {
        g_z1inv[b * LCC + i0 + t] = 1.f / (z1s[t][0] + z1s[t][1]);
        g_z2p[blockIdx.x][b * LQQ + t] = z2s[t][0] + z2s[t][1] + z2s[t][2] + z2s[t][3];
    }
}

// ---------------------------------------------------------------------------
// K3: T numerator partials.  Tnum[j,d] = sum_i E[i,j] * (c*cmf)[i,d].
// Per block: M=128 j, N=128 d, K=256 i (one of NSL slices). A=E^T via
// trans-ldsm, B=(c*cmf) via trans-ldsm. Warps 4(m)x2(n), tile 32x64.
// ---------------------------------------------------------------------------
__global__ __launch_bounds__(256) void k3_T() {
    int b = blockIdx.y, sl = blockIdx.x;
    int kb = sl * (LCC / NSL);
    __shared__ __half E_s[64 * LDH];
    __shared__ __half c_s[64 * LDH];
    int t = threadIdx.x, lane = t & 31, wp = t >> 5, wm = wp >> 1, wn = wp & 1;
    float acc[2][8][4];
#pragma unroll
    for (int a = 0; a < 2; a++)
#pragma unroll
        for (int c = 0; c < 8; c++)
#pragma unroll
            for (int k = 0; k < 4; k++) acc[a][c][k] = 0.f;

    unsigned aB = sm_addr(&E_s[((lane & 7) + 8 * ((lane >> 4) & 1)) * LDH
                               + wm * 32 + 8 * ((lane >> 3) & 1)]);
    unsigned bB = sm_addr(&c_s[((lane & 7) + 8 * ((lane >> 3) & 1)) * LDH
                               + wn * 64 + 8 * ((lane >> 4) & 1)]);
    for (int kc = 0; kc < LCC / NSL; kc += 64) {
        const uint4* gE = (const uint4*)(g_Eh + ((size_t)(b * LCC + kb + kc)) * LQQ);
        const uint4* gC = (const uint4*)(g_ch + ((size_t)(b * LCC + kb + kc)) * DDIM);
#pragma unroll
        for (int l = 0; l < 4; l++) {
            int u = t + l * 256, row = u >> 4, c16 = u & 15;
            *(uint4*)&E_s[row * LDH + c16 * 8] = gE[u];
            *(uint4*)&c_s[row * LDH + c16 * 8] = gC[u];
        }
        __syncthreads();
#pragma unroll
        for (int ks = 0; ks < 4; ks++) {
            unsigned A[2][4];
            ldsm_x4t(aB + ks * (16 * LDH * 2),      A[0][0], A[0][1], A[0][2], A[0][3]);
            ldsm_x4t(aB + ks * (16 * LDH * 2) + 32, A[1][0], A[1][1], A[1][2], A[1][3]);
            unsigned Bf[8][2];
#pragma unroll
            for (int np = 0; np < 4; np++) {
                unsigned r0, r1, r2, r3;
                ldsm_x4t(bB + ks * (16 * LDH * 2) + np * 32, r0, r1, r2, r3);
                Bf[2 * np][0] = r0; Bf[2 * np][1] = r1;
                Bf[2 * np + 1][0] = r2; Bf[2 * np + 1][1] = r3;
            }
#pragma unroll
            for (int a = 0; a < 2; a++)
#pragma unroll
                for (int c = 0; c < 8; c++)
                    mma16816(acc[a][c][0], acc[a][c][1], acc[a][c][2], acc[a][c][3],
                             A[a][0], A[a][1], A[a][2], A[a][3], Bf[c][0], Bf[c][1]);
        }
        __syncthreads();
    }
    int g = lane >> 2, q4 = lane & 3;
#pragma unroll
    for (int a = 0; a < 2; a++) {
        int j0 = wm * 32 + a * 16 + g;
        float* d0 = g_Tp[sl] + ((size_t)(b * LQQ + j0)) * DDIM;
        float* d1 = d0 + 8 * DDIM;
#pragma unroll
        for (int c = 0; c < 8; c++) {
            int col = wn * 64 + c * 8 + 2 * q4;
            *(float2*)(d0 + col) = make_float2(acc[a][c][0], acc[a][c][1]);
            *(float2*)(d1 + col) = make_float2(acc[a][c][2], acc[a][c][3]);
        }
    }
}

// ---------------------------------------------------------------------------
// K3r: T[b,j,d] = qmf[j] * (sum_s num) / (sum_it z2p)  -> fp16 g_Tm
// ---------------------------------------------------------------------------
__global__ __launch_bounds__(128) void k3_red(const int* __restrict__ q_mask) {
    int row = blockIdx.x;      // b*LQQ + j
    int d = threadIdx.x;
    __shared__ float sz[8];
    if (d < 8) sz[d] = g_z2p[d][row];
    __syncthreads();
    float z2 = sz[0] + sz[1] + sz[2] + sz[3] + sz[4] + sz[5] + sz[6] + sz[7];
    float num = 0.f;
#pragma unroll
    for (int s = 0; s < NSL; s++) num += g_Tp[s][(size_t)row * DDIM + d];
    float qmf = q_mask[row] ? 0.f : 1.f;
    g_Tm[(size_t)row * DDIM + d] = __float2half(qmf * num / z2);
}

// ---------------------------------------------------------------------------
// K4: fused dual GEMM A = (E·qmh)/z1, Batt = (E·Tm)/z1, epilogue writes
// out = [c, A, c*A, c*Batt].  M=128 i, N=128 d, K=128 j. A-frags shared.
// ---------------------------------------------------------------------------
__global__ __launch_bounds__(256) void k4_out(const float* __restrict__ c_rep,
                                              float* __restrict__ out) {
    int b = blockIdx.y, i0 = blockIdx.x * 128;
    extern __shared__ __half sm4[];
    __half* E_s = sm4;                  // rows i, cols j (A, non-trans)
    __half* q_s = sm4 + 128 * LDH;      // rows j, cols d (B, trans)
    __half* t_s = sm4 + 2 * 128 * LDH;  // rows j, cols d (B, trans)
    int t = threadIdx.x, lane = t & 31, wp = t >> 5, wm = wp >> 1, wn = wp & 1;
    const uint4* gE = (const uint4*)(g_Eh + ((size_t)(b * LCC + i0)) * LQQ);
    const uint4* gQ = (const uint4*)(g_qmh + (size_t)b * LQQ * DDIM);
    const uint4* gT = (const uint4*)(g_Tm + (size_t)b * LQQ * DDIM);
#pragma unroll
    for (int l = 0; l < 8; l++) {
        int u = t + l * 256, row = u >> 4, c16 = u & 15;
        *(uint4*)&E_s[row * LDH + c16 * 8] = gE[u];
        *(uint4*)&q_s[row * LDH + c16 * 8] = gQ[u];
        *(uint4*)&t_s[row * LDH + c16 * 8] = gT[u];
    }
    __syncthreads();

    float accA[2][8][4], accB[2][8][4];
#pragma unroll
    for (int a = 0; a < 2; a++)
#pragma unroll
        for (int c = 0; c < 8; c++)
#pragma unroll
            for (int k = 0; k < 4; k++) { accA[a][c][k] = 0.f; accB[a][c][k] = 0.f; }

    unsigned aB = sm_addr(&E_s[(wm * 32 + (lane & 15)) * LDH + 8 * (lane >> 4)]);
    unsigned qB = sm_addr(&q_s[((lane & 7) + 8 * ((lane >> 3) & 1)) * LDH
                               + wn * 64 + 8 * ((lane >> 4) & 1)]);
    unsigned tB = sm_addr(&t_s[((lane & 7) + 8 * ((lane >> 3) & 1)) * LDH
                               + wn * 64 + 8 * ((lane >> 4) & 1)]);
#pragma unroll
    for (int ks = 0; ks < 8; ks++) {
        unsigned A[2][4];
        ldsm_x4(aB + ks * 32,                A[0][0], A[0][1], A[0][2], A[0][3]);
        ldsm_x4(aB + 16 * LDH * 2 + ks * 32, A[1][0], A[1][1], A[1][2], A[1][3]);
#pragma unroll
        for (int np = 0; np < 4; np++) {
            unsigned r0, r1, r2, r3;
            ldsm_x4t(qB + ks * (16 * LDH * 2) + np * 32, r0, r1, r2, r3);
#pragma unroll
            for (int a = 0; a < 2; a++) {
                mma16816(accA[a][2 * np][0], accA[a][2 * np][1], accA[a][2 * np][2], accA[a][2 * np][3],
                         A[a][0], A[a][1], A[a][2], A[a][3], r0, r1);
                mma16816(accA[a][2 * np + 1][0], accA[a][2 * np + 1][1], accA[a][2 * np + 1][2], accA[a][2 * np + 1][3],
                         A[a][0], A[a][1], A[a][2], A[a][3], r2, r3);
            }
            ldsm_x4t(tB + ks * (16 * LDH * 2) + np * 32, r0, r1, r2, r3);
#pragma unroll
            for (int a = 0; a < 2; a++) {
                mma16816(accB[a][2 * np][0], accB[a][2 * np][1], accB[a][2 * np][2], accB[a][2 * np][3],
                         A[a][0], A[a][1], A[a][2], A[a][3], r0, r1);
                mma16816(accB[a][2 * np + 1][0], accB[a][2 * np + 1][1], accB[a][2 * np + 1][2], accB[a][2 * np + 1][3],
                         A[a][0], A[a][1], A[a][2], A[a][3], r2, r3);
            }
        }
    }

    int g = lane >> 2, q4 = lane & 3;
#pragma unroll
    for (int a = 0; a < 2; a++) {
        int lr0 = wm * 32 + a * 16 + g;
        size_t gr0 = (size_t)(b * LCC + i0 + lr0);
        size_t gr1 = gr0 + 8;
        float z0 = g_z1inv[gr0], z1v = g_z1inv[gr1];
        const float* cp0 = c_rep + gr0 * DDIM;
        const float* cp1 = c_rep + gr1 * DDIM;
        float* o0 = out + gr0 * (4 * DDIM);
        float* o1 = out + gr1 * (4 * DDIM);
#pragma unroll
        for (int c = 0; c < 8; c++) {
            int col = wn * 64 + c * 8 + 2 * q4;
            float2 cv0 = *(const float2*)(cp0 + col);
            float2 cv1 = *(const float2*)(cp1 + col);
            float2 av0 = make_float2(accA[a][c][0] * z0, accA[a][c][1] * z0);
            float2 av1 = make_float2(accA[a][c][2] * z1v, accA[a][c][3] * z1v);
            float2 bv0 = make_float2(accB[a][c][0] * z0, accB[a][c][1] * z0);
            float2 bv1 = make_float2(accB[a][c][2] * z1v, accB[a][c][3] * z1v);
            *(float2*)(o0 + col) = cv0;
            *(float2*)(o1 + col) = cv1;
            *(float2*)(o0 + DDIM + col) = av0;
            *(float2*)(o1 + DDIM + col) = av1;
            *(float2*)(o0 + 2 * DDIM + col) = make_float2(cv0.x * av0.x, cv0.y * av0.y);
            *(float2*)(o1 + 2 * DDIM + col) = make_float2(cv1.x * av1.x, cv1.y * av1.y);
            *(float2*)(o0 + 3 * DDIM + col) = make_float2(cv0.x * bv0.x, cv0.y * bv0.y);
            *(float2*)(o1 + 3 * DDIM + col) = make_float2(cv1.x * bv1.x, cv1.y * bv1.y);
        }
    }
}

// ---------------------------------------------------------------------------
extern "C" void kernel_launch(void* const* d_in, const int* in_sizes, int n_in,
                              void* d_out, int out_size) {
    const float* c_rep  = (const float*)d_in[0];
    const float* q_rep  = (const float*)d_in[1];
    const int*   c_mask = (const int*)d_in[2];
    const int*   q_mask = (const int*)d_in[3];
    const float* w      = (const float*)d_in[4];
    float* out = (float*)d_out;

    k0_prep<<<(BB * LCC + BB * LQQ) / 8, 256>>>(c_rep, q_rep, c_mask, q_mask, w);
    {
        int smem = 2 * 128 * LDH * 2;  // 69632
        cudaFuncSetAttribute(k2_SE, cudaFuncAttributeMaxDynamicSharedMemorySize, smem);
        dim3 gr(8, BB);
        k2_SE<<<gr, 256, smem>>>(c_mask, q_mask);
    }
    {
        dim3 gr(NSL, BB);
        k3_T<<<gr, 256>>>();
    }
    k3_red<<<BB * LQQ, 128>>>(q_mask);
    {
        int smem = 3 * 128 * LDH * 2;  // 104448
        cudaFuncSetAttribute(k4_out, cudaFuncAttributeMaxDynamicSharedMemorySize, smem);
        dim3 gr(8, BB);
        k4_out<<<gr, 256, smem>>>(c_rep, out);
    }
}

// round 4
// speedup vs baseline: 3.9668x; 1.1603x over previous
#include <cuda_runtime.h>
#include <cuda_fp16.h>
#include <math.h>

#define BB 64
#define LCC 1024
#define LQQ 128
#define DDIM 128
#define LDH 136        // smem row stride in halfs (272B)
#define LDHC 72        // k3 c-slab row stride in halfs (144B)

// ---- device scratch (allocation-free) ----
__device__ __half g_ch [(size_t)BB * LCC * DDIM];  // fp16(c)
__device__ __half g_qwh[BB * LQQ * DDIM];          // fp16(q * w3)
__device__ __half g_qmh[BB * LQQ * DDIM];          // fp16(q * qmf)
__device__ __half g_Eh [(size_t)BB * LCC * LQQ];   // fp16(exp(S))
__device__ __half g_Tm [BB * LQQ * DDIM];          // fp16(T * qmf)
__device__ float  g_cw1[BB * LCC];
__device__ float  g_qw2[BB * LQQ];
__device__ float  g_z1inv[BB * LCC];
__device__ float  g_z2p[8][BB * LQQ];              // col-sum partials per i-tile

// ---- mma / ldmatrix / cp.async helpers ----
__device__ __forceinline__ unsigned sm_addr(const void* p) {
    return (unsigned)__cvta_generic_to_shared(p);
}
__device__ __forceinline__ void ldsm_x4(unsigned a, unsigned& r0, unsigned& r1,
                                        unsigned& r2, unsigned& r3) {
    asm volatile("ldmatrix.sync.aligned.m8n8.x4.shared.b16 {%0,%1,%2,%3}, [%4];"
                 : "=r"(r0), "=r"(r1), "=r"(r2), "=r"(r3) : "r"(a));
}
__device__ __forceinline__ void ldsm_x4t(unsigned a, unsigned& r0, unsigned& r1,
                                         unsigned& r2, unsigned& r3) {
    asm volatile("ldmatrix.sync.aligned.m8n8.x4.trans.shared.b16 {%0,%1,%2,%3}, [%4];"
                 : "=r"(r0), "=r"(r1), "=r"(r2), "=r"(r3) : "r"(a));
}
__device__ __forceinline__ void mma16816(float& c0, float& c1, float& c2, float& c3,
                                         unsigned a0, unsigned a1, unsigned a2, unsigned a3,
                                         unsigned b0, unsigned b1) {
    asm volatile(
        "mma.sync.aligned.m16n8k16.row.col.f32.f16.f16.f32 "
        "{%0,%1,%2,%3}, {%4,%5,%6,%7}, {%8,%9}, {%0,%1,%2,%3};"
        : "+f"(c0), "+f"(c1), "+f"(c2), "+f"(c3)
        : "r"(a0), "r"(a1), "r"(a2), "r"(a3), "r"(b0), "r"(b1));
}
__device__ __forceinline__ void cp_async16(unsigned saddr, const void* g) {
    asm volatile("cp.async.cg.shared.global [%0], [%1], 16;" :: "r"(saddr), "l"(g));
}
__device__ __forceinline__ void cp_commit() {
    asm volatile("cp.async.commit_group;");
}
template <int N> __device__ __forceinline__ void cp_wait() {
    asm volatile("cp.async.wait_group %0;" :: "n"(N));
}
__device__ __forceinline__ unsigned hmul2u(unsigned a, __half2 s) {
    __half2 r = __hmul2(*(__half2*)&a, s);
    return *(unsigned*)&r;
}

// ---------------------------------------------------------------------------
// K0: warp per row. cw1/qw2 fp32 dots; fp16 conversions: c plain, q*w3, q*qmf.
// ---------------------------------------------------------------------------
__global__ __launch_bounds__(256) void k0_prep(const float* __restrict__ c_rep,
                                               const float* __restrict__ q_rep,
                                               const int* __restrict__ q_mask,
                                               const float* __restrict__ w) {
    int gw   = (blockIdx.x * 256 + threadIdx.x) >> 5;
    int lane = threadIdx.x & 31;
    const int NC = BB * LCC;
    if (gw < NC) {
        float4 cv = *(const float4*)(c_rep + (size_t)gw * DDIM + lane * 4);
        float4 w1 = *(const float4*)(w + lane * 4);
        float s = cv.x * w1.x + cv.y * w1.y + cv.z * w1.z + cv.w * w1.w;
#pragma unroll
        for (int o = 16; o > 0; o >>= 1) s += __shfl_xor_sync(~0u, s, o);
        if (lane == 0) g_cw1[gw] = s;
        __half2 a0 = __floats2half2_rn(cv.x, cv.y);
        __half2 a1 = __floats2half2_rn(cv.z, cv.w);
        uint2 u; u.x = *(unsigned*)&a0; u.y = *(unsigned*)&a1;
        *(uint2*)(g_ch + (size_t)gw * DDIM + lane * 4) = u;
    } else if (gw < NC + BB * LQQ) {
        int r = gw - NC;
        float4 qv = *(const float4*)(q_rep + (size_t)r * DDIM + lane * 4);
        float4 w2 = *(const float4*)(w + DDIM + lane * 4);
        float4 w3 = *(const float4*)(w + 2 * DDIM + lane * 4);
        float s = qv.x * w2.x + qv.y * w2.y + qv.z * w2.z + qv.w * w2.w;
#pragma unroll
        for (int o = 16; o > 0; o >>= 1) s += __shfl_xor_sync(~0u, s, o);
        if (lane == 0) g_qw2[r] = s;
        __half2 a0 = __floats2half2_rn(qv.x * w3.x, qv.y * w3.y);
        __half2 a1 = __floats2half2_rn(qv.z * w3.z, qv.w * w3.w);
        uint2 u; u.x = *(unsigned*)&a0; u.y = *(unsigned*)&a1;
        *(uint2*)(g_qwh + (size_t)r * DDIM + lane * 4) = u;
        float mf = q_mask[r] ? 0.f : 1.f;
        __half2 m0 = __floats2half2_rn(qv.x * mf, qv.y * mf);
        __half2 m1 = __floats2half2_rn(qv.z * mf, qv.w * mf);
        uint2 v; v.x = *(unsigned*)&m0; v.y = *(unsigned*)&m1;
        *(uint2*)(g_qmh + (size_t)r * DDIM + lane * 4) = v;
    }
}

// ---------------------------------------------------------------------------
// K2: S = cw1 + qw2 + c·(q*w3)^T  (M=128 i, N=128 j, K=128 d), E=exp(S) fp16,
// z1inv finalized, z2 partials staged. Warps 4(m)x2(n), warp tile 32x64.
// ---------------------------------------------------------------------------
__global__ __launch_bounds__(256) void k2_SE(const int* __restrict__ c_mask,
                                             const int* __restrict__ q_mask) {
    int b = blockIdx.y, i0 = blockIdx.x * 128;
    extern __shared__ __half sm2[];
    __half* cw_s = sm2;                // [128][LDH]  A: rows i, cols d
    __half* q_s  = sm2 + 128 * LDH;    // [128][LDH]  B: rows j, cols d
    __shared__ float z1s[128][2];
    __shared__ float z2s[128][4];
    __shared__ float qmf_s[128], cmf_s[128];
    __shared__ float cw1_s[128], qw2_s[128];
    int t = threadIdx.x, lane = t & 31, wp = t >> 5, wm = wp >> 1, wn = wp & 1;
    if (t < 128) {
        qmf_s[t] = q_mask[b * LQQ + t] ? 0.f : 1.f;
        cmf_s[t] = c_mask[b * LCC + i0 + t] ? 0.f : 1.f;
        cw1_s[t] = g_cw1[b * LCC + i0 + t];
        qw2_s[t] = g_qw2[b * LQQ + t];
    }
    const uint4* gc = (const uint4*)(g_ch + ((size_t)(b * LCC + i0)) * DDIM);
    const uint4* gq = (const uint4*)(g_qwh + (size_t)b * LQQ * DDIM);
#pragma unroll
    for (int l = 0; l < 8; l++) {
        int u = t + l * 256, row = u >> 4, c16 = u & 15;
        *(uint4*)&cw_s[row * LDH + c16 * 8] = gc[u];
        *(uint4*)&q_s [row * LDH + c16 * 8] = gq[u];
    }
    __syncthreads();

    float acc[2][8][4];
#pragma unroll
    for (int a = 0; a < 2; a++)
#pragma unroll
        for (int c = 0; c < 8; c++)
#pragma unroll
            for (int k = 0; k < 4; k++) acc[a][c][k] = 0.f;

    unsigned aB = sm_addr(&cw_s[(wm * 32 + (lane & 15)) * LDH + 8 * (lane >> 4)]);
    unsigned bB = sm_addr(&q_s[(wn * 64 + 8 * ((lane >> 4) & 1) + (lane & 7)) * LDH
                               + 8 * ((lane >> 3) & 1)]);
#pragma unroll
    for (int ks = 0; ks < 8; ks++) {
        unsigned A[2][4];
        ldsm_x4(aB + ks * 32,                 A[0][0], A[0][1], A[0][2], A[0][3]);
        ldsm_x4(aB + 16 * LDH * 2 + ks * 32,  A[1][0], A[1][1], A[1][2], A[1][3]);
        unsigned Bf[8][2];
#pragma unroll
        for (int np = 0; np < 4; np++) {
            unsigned r0, r1, r2, r3;
            ldsm_x4(bB + np * (16 * LDH * 2) + ks * 32, r0, r1, r2, r3);
            Bf[2 * np][0] = r0; Bf[2 * np][1] = r1;
            Bf[2 * np + 1][0] = r2; Bf[2 * np + 1][1] = r3;
        }
#pragma unroll
        for (int a = 0; a < 2; a++)
#pragma unroll
            for (int c = 0; c < 8; c++)
                mma16816(acc[a][c][0], acc[a][c][1], acc[a][c][2], acc[a][c][3],
                         A[a][0], A[a][1], A[a][2], A[a][3], Bf[c][0], Bf[c][1]);
    }

    // epilogue: add rank-1 terms, exp, store E, accumulate z1/z2
    int g = lane >> 2, q4 = lane & 3;
    float z1a[2][2] = {{0.f, 0.f}, {0.f, 0.f}};
    float z2a[8][2];
#pragma unroll
    for (int c = 0; c < 8; c++) { z2a[c][0] = 0.f; z2a[c][1] = 0.f; }
#pragma unroll
    for (int a = 0; a < 2; a++) {
        int lr0 = wm * 32 + a * 16 + g;
        float cwv0 = cw1_s[lr0], cwv1 = cw1_s[lr0 + 8];
        float cmf0 = cmf_s[lr0], cmf1 = cmf_s[lr0 + 8];
        __half* e0p = g_Eh + ((size_t)(b * LCC + i0 + lr0)) * LQQ;
        __half* e1p = e0p + 8 * LQQ;
#pragma unroll
        for (int c = 0; c < 8; c++) {
            int col = wn * 64 + c * 8 + 2 * q4;
            float qw0 = qw2_s[col], qw1 = qw2_s[col + 1];
            float qf0 = qmf_s[col], qf1 = qmf_s[col + 1];
            float s0 = acc[a][c][0] + cwv0 + qw0;
            float s1 = acc[a][c][1] + cwv0 + qw1;
            float s2 = acc[a][c][2] + cwv1 + qw0;
            float s3 = acc[a][c][3] + cwv1 + qw1;
            __half h0 = __float2half(__expf(s0));
            __half h1 = __float2half(__expf(s1));
            __half h2 = __float2half(__expf(s2));
            __half h3 = __float2half(__expf(s3));
            *(__half2*)(e0p + col) = __halves2half2(h0, h1);
            *(__half2*)(e1p + col) = __halves2half2(h2, h3);
            float e0 = __half2float(h0), e1 = __half2float(h1);
            float e2 = __half2float(h2), e3 = __half2float(h3);
            z1a[a][0] += qf0 * e0 + qf1 * e1;
            z1a[a][1] += qf0 * e2 + qf1 * e3;
            z2a[c][0] += cmf0 * e0 + cmf1 * e2;
            z2a[c][1] += cmf0 * e1 + cmf1 * e3;
        }
    }
#pragma unroll
    for (int a = 0; a < 2; a++)
#pragma unroll
        for (int h = 0; h < 2; h++) {
            float v = z1a[a][h];
            v += __shfl_xor_sync(~0u, v, 1);
            v += __shfl_xor_sync(~0u, v, 2);
            if (q4 == 0) z1s[wm * 32 + a * 16 + g + 8 * h][wn] = v;
        }
#pragma unroll
    for (int c = 0; c < 8; c++)
#pragma unroll
        for (int s = 0; s < 2; s++) {
            float v = z2a[c][s];
            v += __shfl_xor_sync(~0u, v, 4);
            v += __shfl_xor_sync(~0u, v, 8);
            v += __shfl_xor_sync(~0u, v, 16);
            if (g == 0) z2s[wn * 64 + c * 8 + 2 * q4 + s][wm] = v;
        }
    __syncthreads();
    if (t < 128) {
        g_z1inv[b * LCC + i0 + t] = 1.f / (z1s[t][0] + z1s[t][1]);
        g_z2p[blockIdx.x][b * LQQ + t] = z2s[t][0] + z2s[t][1] + z2s[t][2] + z2s[t][3];
    }
}

// ---------------------------------------------------------------------------
// K3: T[j,d] = qmf[j]/z2[j] * sum_i cmf[i]*E[i,j]*c[i,d]  -> fp16 g_Tm
// N-split over d halves: grid (2, BB). M=128 j, N=64 d, K=1024 i.
// cp.async double-buffered (64-i chunks). cmf applied by scaling A-frags.
// Warps 4(m)x2(n): warp tile 32j x 32d.
// ---------------------------------------------------------------------------
#define EBUFB (64 * LDH * 2)    // bytes per E buffer
#define CBUFB (64 * LDHC * 2)   // bytes per c buffer
__global__ __launch_bounds__(256) void k3_T(const int* __restrict__ c_mask,
                                            const int* __restrict__ q_mask) {
    int b = blockIdx.y, d0 = blockIdx.x * 64;
    extern __shared__ __half s3[];
    __half* E_s   = s3;                         // 2 x 64 x LDH
    __half* c_s   = s3 + 2 * 64 * LDH;          // 2 x 64 x LDHC
    __half* cmf_s = s3 + 2 * 64 * LDH + 2 * 64 * LDHC;  // 1024
    float*  f_s   = (float*)(cmf_s + 1024);     // 128
    int t = threadIdx.x, lane = t & 31, wp = t >> 5, wm = wp >> 1, wn = wp & 1;

    unsigned Ebase = sm_addr(E_s);
    unsigned Cbase = sm_addr(c_s);
    // prefetch chunk 0
    {
        const char* gE = (const char*)(g_Eh + ((size_t)b * LCC) * LQQ);
        const char* gC = (const char*)(g_ch + ((size_t)b * LCC) * DDIM + d0);
#pragma unroll
        for (int l = 0; l < 4; l++) {
            int u = t + l * 256, row = u >> 4, c16 = u & 15;
            cp_async16(Ebase + (row * LDH + c16 * 8) * 2, gE + ((size_t)row * LQQ + c16 * 8) * 2);
        }
#pragma unroll
        for (int l = 0; l < 2; l++) {
            int u = t + l * 256, row = u >> 3, c8 = u & 7;
            cp_async16(Cbase + (row * LDHC + c8 * 8) * 2, gC + ((size_t)row * DDIM + c8 * 8) * 2);
        }
        cp_commit();
    }
    // cmf halfs for all 1024 i; f_s = qmf/z2 per j
#pragma unroll
    for (int l = 0; l < 4; l++) {
        int i = t + l * 256;
        cmf_s[i] = __float2half(c_mask[b * LCC + i] ? 0.f : 1.f);
    }
    if (t < 128) {
        float z2 = 0.f;
#pragma unroll
        for (int s = 0; s < 8; s++) z2 += g_z2p[s][b * LQQ + t];
        f_s[t] = q_mask[b * LQQ + t] ? 0.f : (1.f / z2);
    }

    float acc[2][4][4];
#pragma unroll
    for (int a = 0; a < 2; a++)
#pragma unroll
        for (int c = 0; c < 4; c++)
#pragma unroll
            for (int k = 0; k < 4; k++) acc[a][c][k] = 0.f;

    unsigned aB = Ebase + (((lane & 7) + 8 * ((lane >> 4) & 1)) * LDH
                           + wm * 32 + 8 * ((lane >> 3) & 1)) * 2;
    unsigned bB = Cbase + (((lane & 7) + 8 * ((lane >> 3) & 1)) * LDHC
                           + wn * 32 + 8 * ((lane >> 4) & 1)) * 2;

    for (int kc = 0; kc < 16; kc++) {
        int buf = kc & 1;
        if (kc + 1 < 16) {
            int nxt = buf ^ 1;
            const char* gE = (const char*)(g_Eh + ((size_t)(b * LCC + (kc + 1) * 64)) * LQQ);
            const char* gC = (const char*)(g_ch + ((size_t)(b * LCC + (kc + 1) * 64)) * DDIM + d0);
#pragma unroll
            for (int l = 0; l < 4; l++) {
                int u = t + l * 256, row = u >> 4, c16 = u & 15;
                cp_async16(Ebase + nxt * EBUFB + (row * LDH + c16 * 8) * 2,
                           gE + ((size_t)row * LQQ + c16 * 8) * 2);
            }
#pragma unroll
            for (int l = 0; l < 2; l++) {
                int u = t + l * 256, row = u >> 3, c8 = u & 7;
                cp_async16(Cbase + nxt * CBUFB + (row * LDHC + c8 * 8) * 2,
                           gC + ((size_t)row * DDIM + c8 * 8) * 2);
            }
            cp_commit();
            cp_wait<1>();
        } else {
            cp_wait<0>();
        }
        __syncthreads();
#pragma unroll
        for (int ks = 0; ks < 4; ks++) {
            int ibase = kc * 64 + ks * 16;
            __half2 cm_lo = *(__half2*)&cmf_s[ibase + (lane & 3) * 2];
            __half2 cm_hi = *(__half2*)&cmf_s[ibase + 8 + (lane & 3) * 2];
            unsigned A[2][4];
            ldsm_x4t(aB + buf * EBUFB + ks * (16 * LDH * 2),      A[0][0], A[0][1], A[0][2], A[0][3]);
            ldsm_x4t(aB + buf * EBUFB + ks * (16 * LDH * 2) + 32, A[1][0], A[1][1], A[1][2], A[1][3]);
#pragma unroll
            for (int a = 0; a < 2; a++) {
                A[a][0] = hmul2u(A[a][0], cm_lo);
                A[a][1] = hmul2u(A[a][1], cm_lo);
                A[a][2] = hmul2u(A[a][2], cm_hi);
                A[a][3] = hmul2u(A[a][3], cm_hi);
            }
            unsigned Bf[4][2];
#pragma unroll
            for (int np = 0; np < 2; np++) {
                unsigned r0, r1, r2, r3;
                ldsm_x4t(bB + buf * CBUFB + ks * (16 * LDHC * 2) + np * 32, r0, r1, r2, r3);
                Bf[2 * np][0] = r0; Bf[2 * np][1] = r1;
                Bf[2 * np + 1][0] = r2; Bf[2 * np + 1][1] = r3;
            }
#pragma unroll
            for (int a = 0; a < 2; a++)
#pragma unroll
                for (int c = 0; c < 4; c++)
                    mma16816(acc[a][c][0], acc[a][c][1], acc[a][c][2], acc[a][c][3],
                             A[a][0], A[a][1], A[a][2], A[a][3], Bf[c][0], Bf[c][1]);
        }
        __syncthreads();
    }

    int g = lane >> 2, q4 = lane & 3;
#pragma unroll
    for (int a = 0; a < 2; a++) {
        int j0 = wm * 32 + a * 16 + g;
        float f0 = f_s[j0], f1 = f_s[j0 + 8];
        __half* o0 = g_Tm + ((size_t)(b * LQQ + j0)) * DDIM + d0;
        __half* o1 = o0 + 8 * DDIM;
#pragma unroll
        for (int c = 0; c < 4; c++) {
            int col = wn * 32 + c * 8 + 2 * q4;
            *(__half2*)(o0 + col) = __floats2half2_rn(acc[a][c][0] * f0, acc[a][c][1] * f0);
            *(__half2*)(o1 + col) = __floats2half2_rn(acc[a][c][2] * f1, acc[a][c][3] * f1);
        }
    }
}

// ---------------------------------------------------------------------------
// K4: fused dual GEMM A = (E·qmh)/z1, Batt = (E·Tm)/z1, epilogue writes
// out = [c, A, c*A, c*Batt].  M=128 i, N=128 d, K=128 j. A-frags shared.
// ---------------------------------------------------------------------------
__global__ __launch_bounds__(256) void k4_out(const float* __restrict__ c_rep,
                                              float* __restrict__ out) {
    int b = blockIdx.y, i0 = blockIdx.x * 128;
    extern __shared__ __half sm4[];
    __half* E_s = sm4;                  // rows i, cols j (A, non-trans)
    __half* q_s = sm4 + 128 * LDH;      // rows j, cols d (B, trans)
    __half* t_s = sm4 + 2 * 128 * LDH;  // rows j, cols d (B, trans)
    int t = threadIdx.x, lane = t & 31, wp = t >> 5, wm = wp >> 1, wn = wp & 1;
    const uint4* gE = (const uint4*)(g_Eh + ((size_t)(b * LCC + i0)) * LQQ);
    const uint4* gQ = (const uint4*)(g_qmh + (size_t)b * LQQ * DDIM);
    const uint4* gT = (const uint4*)(g_Tm + (size_t)b * LQQ * DDIM);
#pragma unroll
    for (int l = 0; l < 8; l++) {
        int u = t + l * 256, row = u >> 4, c16 = u & 15;
        *(uint4*)&E_s[row * LDH + c16 * 8] = gE[u];
        *(uint4*)&q_s[row * LDH + c16 * 8] = gQ[u];
        *(uint4*)&t_s[row * LDH + c16 * 8] = gT[u];
    }
    __syncthreads();

    float accA[2][8][4], accB[2][8][4];
#pragma unroll
    for (int a = 0; a < 2; a++)
#pragma unroll
        for (int c = 0; c < 8; c++)
#pragma unroll
            for (int k = 0; k < 4; k++) { accA[a][c][k] = 0.f; accB[a][c][k] = 0.f; }

    unsigned aB = sm_addr(&E_s[(wm * 32 + (lane & 15)) * LDH + 8 * (lane >> 4)]);
    unsigned qB = sm_addr(&q_s[((lane & 7) + 8 * ((lane >> 3) & 1)) * LDH
                               + wn * 64 + 8 * ((lane >> 4) & 1)]);
    unsigned tB = sm_addr(&t_s[((lane & 7) + 8 * ((lane >> 3) & 1)) * LDH
                               + wn * 64 + 8 * ((lane >> 4) & 1)]);
#pragma unroll
    for (int ks = 0; ks < 8; ks++) {
        unsigned A[2][4];
        ldsm_x4(aB + ks * 32,                A[0][0], A[0][1], A[0][2], A[0][3]);
        ldsm_x4(aB + 16 * LDH * 2 + ks * 32, A[1][0], A[1][1], A[1][2], A[1][3]);
#pragma unroll
        for (int np = 0; np < 4; np++) {
            unsigned r0, r1, r2, r3;
            ldsm_x4t(qB + ks * (16 * LDH * 2) + np * 32, r0, r1, r2, r3);
#pragma unroll
            for (int a = 0; a < 2; a++) {
                mma16816(accA[a][2 * np][0], accA[a][2 * np][1], accA[a][2 * np][2], accA[a][2 * np][3],
                         A[a][0], A[a][1], A[a][2], A[a][3], r0, r1);
                mma16816(accA[a][2 * np + 1][0], accA[a][2 * np + 1][1], accA[a][2 * np + 1][2], accA[a][2 * np + 1][3],
                         A[a][0], A[a][1], A[a][2], A[a][3], r2, r3);
            }
            ldsm_x4t(tB + ks * (16 * LDH * 2) + np * 32, r0, r1, r2, r3);
#pragma unroll
            for (int a = 0; a < 2; a++) {
                mma16816(accB[a][2 * np][0], accB[a][2 * np][1], accB[a][2 * np][2], accB[a][2 * np][3],
                         A[a][0], A[a][1], A[a][2], A[a][3], r0, r1);
                mma16816(accB[a][2 * np + 1][0], accB[a][2 * np + 1][1], accB[a][2 * np + 1][2], accB[a][2 * np + 1][3],
                         A[a][0], A[a][1], A[a][2], A[a][3], r2, r3);
            }
        }
    }

    int g = lane >> 2, q4 = lane & 3;
#pragma unroll
    for (int a = 0; a < 2; a++) {
        int lr0 = wm * 32 + a * 16 + g;
        size_t gr0 = (size_t)(b * LCC + i0 + lr0);
        size_t gr1 = gr0 + 8;
        float z0 = g_z1inv[gr0], z1v = g_z1inv[gr1];
        const float* cp0 = c_rep + gr0 * DDIM;
        const float* cp1 = c_rep + gr1 * DDIM;
        float* o0 = out + gr0 * (4 * DDIM);
        float* o1 = out + gr1 * (4 * DDIM);
#pragma unroll
        for (int c = 0; c < 8; c++) {
            int col = wn * 64 + c * 8 + 2 * q4;
            float2 cv0 = *(const float2*)(cp0 + col);
            float2 cv1 = *(const float2*)(cp1 + col);
            float2 av0 = make_float2(accA[a][c][0] * z0, accA[a][c][1] * z0);
            float2 av1 = make_float2(accA[a][c][2] * z1v, accA[a][c][3] * z1v);
            float2 bv0 = make_float2(accB[a][c][0] * z0, accB[a][c][1] * z0);
            float2 bv1 = make_float2(accB[a][c][2] * z1v, accB[a][c][3] * z1v);
            *(float2*)(o0 + col) = cv0;
            *(float2*)(o1 + col) = cv1;
            *(float2*)(o0 + DDIM + col) = av0;
            *(float2*)(o1 + DDIM + col) = av1;
            *(float2*)(o0 + 2 * DDIM + col) = make_float2(cv0.x * av0.x, cv0.y * av0.y);
            *(float2*)(o1 + 2 * DDIM + col) = make_float2(cv1.x * av1.x, cv1.y * av1.y);
            *(float2*)(o0 + 3 * DDIM + col) = make_float2(cv0.x * bv0.x, cv0.y * bv0.y);
            *(float2*)(o1 + 3 * DDIM + col) = make_float2(cv1.x * bv1.x, cv1.y * bv1.y);
        }
    }
}

// ---------------------------------------------------------------------------
extern "C" void kernel_launch(void* const* d_in, const int* in_sizes, int n_in,
                              void* d_out, int out_size) {
    const float* c_rep  = (const float*)d_in[0];
    const float* q_rep  = (const float*)d_in[1];
    const int*   c_mask = (const int*)d_in[2];
    const int*   q_mask = (const int*)d_in[3];
    const float* w      = (const float*)d_in[4];
    float* out = (float*)d_out;

    k0_prep<<<(BB * LCC + BB * LQQ) / 8, 256>>>(c_rep, q_rep, q_mask, w);
    {
        int smem = 2 * 128 * LDH * 2;  // 69632
        cudaFuncSetAttribute(k2_SE, cudaFuncAttributeMaxDynamicSharedMemorySize, smem);
        dim3 gr(8, BB);
        k2_SE<<<gr, 256, smem>>>(c_mask, q_mask);
    }
    {
        int smem = 2 * EBUFB + 2 * CBUFB + 1024 * 2 + 128 * 4;  // 55808
        cudaFuncSetAttribute(k3_T, cudaFuncAttributeMaxDynamicSharedMemorySize, smem);
        dim3 gr(2, BB);
        k3_T<<<gr, 256, smem>>>(c_mask, q_mask);
    }
    {
        int smem = 3 * 128 * LDH * 2;  // 104448
        cudaFuncSetAttribute(k4_out, cudaFuncAttributeMaxDynamicSharedMemorySize, smem);
        dim3 gr(8, BB);
        k4_out<<<gr, 256, smem>>>(c_rep, out);
    }
}

// round 5
// speedup vs baseline: 4.3296x; 1.0915x over previous
#include <cuda_runtime.h>
#include <cuda_fp16.h>
#include <math.h>

#define BB 64
#define LCC 1024
#define LQQ 128
#define DDIM 128
#define LDH 136        // smem row stride in halfs (272B)
#define LDHC 72        // half-width slab row stride in halfs (144B)

// ---- device scratch (allocation-free) ----
__device__ __half g_ch [(size_t)BB * LCC * DDIM];  // fp16(c)
__device__ __half g_qwh[BB * LQQ * DDIM];          // fp16(q * w3)
__device__ __half g_qmh[BB * LQQ * DDIM];          // fp16(q * qmf)
__device__ __half g_Eh [(size_t)BB * LCC * LQQ];   // fp16(exp(S))
__device__ __half g_Tm [BB * LQQ * DDIM];          // fp16(T * qmf)
__device__ float  g_cw1[BB * LCC];
__device__ float  g_qw2[BB * LQQ];
__device__ float  g_z1inv[BB * LCC];
__device__ float  g_z2p[8][BB * LQQ];              // col-sum partials per i-tile

// ---- mma / ldmatrix / cp.async helpers ----
__device__ __forceinline__ unsigned sm_addr(const void* p) {
    return (unsigned)__cvta_generic_to_shared(p);
}
__device__ __forceinline__ void ldsm_x4(unsigned a, unsigned& r0, unsigned& r1,
                                        unsigned& r2, unsigned& r3) {
    asm volatile("ldmatrix.sync.aligned.m8n8.x4.shared.b16 {%0,%1,%2,%3}, [%4];"
                 : "=r"(r0), "=r"(r1), "=r"(r2), "=r"(r3) : "r"(a));
}
__device__ __forceinline__ void ldsm_x4t(unsigned a, unsigned& r0, unsigned& r1,
                                         unsigned& r2, unsigned& r3) {
    asm volatile("ldmatrix.sync.aligned.m8n8.x4.trans.shared.b16 {%0,%1,%2,%3}, [%4];"
                 : "=r"(r0), "=r"(r1), "=r"(r2), "=r"(r3) : "r"(a));
}
__device__ __forceinline__ void mma16816(float& c0, float& c1, float& c2, float& c3,
                                         unsigned a0, unsigned a1, unsigned a2, unsigned a3,
                                         unsigned b0, unsigned b1) {
    asm volatile(
        "mma.sync.aligned.m16n8k16.row.col.f32.f16.f16.f32 "
        "{%0,%1,%2,%3}, {%4,%5,%6,%7}, {%8,%9}, {%0,%1,%2,%3};"
        : "+f"(c0), "+f"(c1), "+f"(c2), "+f"(c3)
        : "r"(a0), "r"(a1), "r"(a2), "r"(a3), "r"(b0), "r"(b1));
}
__device__ __forceinline__ void cp_async16(unsigned saddr, const void* g) {
    asm volatile("cp.async.cg.shared.global [%0], [%1], 16;" :: "r"(saddr), "l"(g));
}
__device__ __forceinline__ void cp_commit() {
    asm volatile("cp.async.commit_group;");
}
template <int N> __device__ __forceinline__ void cp_wait() {
    asm volatile("cp.async.wait_group %0;" :: "n"(N));
}
__device__ __forceinline__ unsigned hmul2u(unsigned a, __half2 s) {
    __half2 r = __hmul2(*(__half2*)&a, s);
    return *(unsigned*)&r;
}

// ---------------------------------------------------------------------------
// K0: warp per row. cw1/qw2 fp32 dots; fp16 conversions: c plain, q*w3, q*qmf.
// ---------------------------------------------------------------------------
__global__ __launch_bounds__(256) void k0_prep(const float* __restrict__ c_rep,
                                               const float* __restrict__ q_rep,
                                               const int* __restrict__ q_mask,
                                               const float* __restrict__ w) {
    int gw   = (blockIdx.x * 256 + threadIdx.x) >> 5;
    int lane = threadIdx.x & 31;
    const int NC = BB * LCC;
    if (gw < NC) {
        float4 cv = *(const float4*)(c_rep + (size_t)gw * DDIM + lane * 4);
        float4 w1 = *(const float4*)(w + lane * 4);
        float s = cv.x * w1.x + cv.y * w1.y + cv.z * w1.z + cv.w * w1.w;
#pragma unroll
        for (int o = 16; o > 0; o >>= 1) s += __shfl_xor_sync(~0u, s, o);
        if (lane == 0) g_cw1[gw] = s;
        __half2 a0 = __floats2half2_rn(cv.x, cv.y);
        __half2 a1 = __floats2half2_rn(cv.z, cv.w);
        uint2 u; u.x = *(unsigned*)&a0; u.y = *(unsigned*)&a1;
        *(uint2*)(g_ch + (size_t)gw * DDIM + lane * 4) = u;
    } else if (gw < NC + BB * LQQ) {
        int r = gw - NC;
        float4 qv = *(const float4*)(q_rep + (size_t)r * DDIM + lane * 4);
        float4 w2 = *(const float4*)(w + DDIM + lane * 4);
        float4 w3 = *(const float4*)(w + 2 * DDIM + lane * 4);
        float s = qv.x * w2.x + qv.y * w2.y + qv.z * w2.z + qv.w * w2.w;
#pragma unroll
        for (int o = 16; o > 0; o >>= 1) s += __shfl_xor_sync(~0u, s, o);
        if (lane == 0) g_qw2[r] = s;
        __half2 a0 = __floats2half2_rn(qv.x * w3.x, qv.y * w3.y);
        __half2 a1 = __floats2half2_rn(qv.z * w3.z, qv.w * w3.w);
        uint2 u; u.x = *(unsigned*)&a0; u.y = *(unsigned*)&a1;
        *(uint2*)(g_qwh + (size_t)r * DDIM + lane * 4) = u;
        float mf = q_mask[r] ? 0.f : 1.f;
        __half2 m0 = __floats2half2_rn(qv.x * mf, qv.y * mf);
        __half2 m1 = __floats2half2_rn(qv.z * mf, qv.w * mf);
        uint2 v; v.x = *(unsigned*)&m0; v.y = *(unsigned*)&m1;
        *(uint2*)(g_qmh + (size_t)r * DDIM + lane * 4) = v;
    }
}

// ---------------------------------------------------------------------------
// K2: S = cw1 + qw2 + c·(q*w3)^T  (M=128 i, N=128 j, K=128 d), E=exp(S) fp16,
// z1inv finalized, z2 partials staged. Warps 4(m)x2(n), warp tile 32x64.
// ---------------------------------------------------------------------------
__global__ __launch_bounds__(256) void k2_SE(const int* __restrict__ c_mask,
                                             const int* __restrict__ q_mask) {
    int b = blockIdx.y, i0 = blockIdx.x * 128;
    extern __shared__ __half sm2[];
    __half* cw_s = sm2;                // [128][LDH]  A: rows i, cols d
    __half* q_s  = sm2 + 128 * LDH;    // [128][LDH]  B: rows j, cols d
    __shared__ float z1s[128][2];
    __shared__ float z2s[128][4];
    __shared__ float qmf_s[128], cmf_s[128];
    __shared__ float cw1_s[128], qw2_s[128];
    int t = threadIdx.x, lane = t & 31, wp = t >> 5, wm = wp >> 1, wn = wp & 1;
    if (t < 128) {
        qmf_s[t] = q_mask[b * LQQ + t] ? 0.f : 1.f;
        cmf_s[t] = c_mask[b * LCC + i0 + t] ? 0.f : 1.f;
        cw1_s[t] = g_cw1[b * LCC + i0 + t];
        qw2_s[t] = g_qw2[b * LQQ + t];
    }
    const uint4* gc = (const uint4*)(g_ch + ((size_t)(b * LCC + i0)) * DDIM);
    const uint4* gq = (const uint4*)(g_qwh + (size_t)b * LQQ * DDIM);
#pragma unroll
    for (int l = 0; l < 8; l++) {
        int u = t + l * 256, row = u >> 4, c16 = u & 15;
        *(uint4*)&cw_s[row * LDH + c16 * 8] = gc[u];
        *(uint4*)&q_s [row * LDH + c16 * 8] = gq[u];
    }
    __syncthreads();

    float acc[2][8][4];
#pragma unroll
    for (int a = 0; a < 2; a++)
#pragma unroll
        for (int c = 0; c < 8; c++)
#pragma unroll
            for (int k = 0; k < 4; k++) acc[a][c][k] = 0.f;

    unsigned aB = sm_addr(&cw_s[(wm * 32 + (lane & 15)) * LDH + 8 * (lane >> 4)]);
    unsigned bB = sm_addr(&q_s[(wn * 64 + 8 * ((lane >> 4) & 1) + (lane & 7)) * LDH
                               + 8 * ((lane >> 3) & 1)]);
#pragma unroll
    for (int ks = 0; ks < 8; ks++) {
        unsigned A[2][4];
        ldsm_x4(aB + ks * 32,                 A[0][0], A[0][1], A[0][2], A[0][3]);
        ldsm_x4(aB + 16 * LDH * 2 + ks * 32,  A[1][0], A[1][1], A[1][2], A[1][3]);
        unsigned Bf[8][2];
#pragma unroll
        for (int np = 0; np < 4; np++) {
            unsigned r0, r1, r2, r3;
            ldsm_x4(bB + np * (16 * LDH * 2) + ks * 32, r0, r1, r2, r3);
            Bf[2 * np][0] = r0; Bf[2 * np][1] = r1;
            Bf[2 * np + 1][0] = r2; Bf[2 * np + 1][1] = r3;
        }
#pragma unroll
        for (int a = 0; a < 2; a++)
#pragma unroll
            for (int c = 0; c < 8; c++)
                mma16816(acc[a][c][0], acc[a][c][1], acc[a][c][2], acc[a][c][3],
                         A[a][0], A[a][1], A[a][2], A[a][3], Bf[c][0], Bf[c][1]);
    }

    // epilogue: add rank-1 terms, exp, store E, accumulate z1/z2
    int g = lane >> 2, q4 = lane & 3;
    float z1a[2][2] = {{0.f, 0.f}, {0.f, 0.f}};
    float z2a[8][2];
#pragma unroll
    for (int c = 0; c < 8; c++) { z2a[c][0] = 0.f; z2a[c][1] = 0.f; }
#pragma unroll
    for (int a = 0; a < 2; a++) {
        int lr0 = wm * 32 + a * 16 + g;
        float cwv0 = cw1_s[lr0], cwv1 = cw1_s[lr0 + 8];
        float cmf0 = cmf_s[lr0], cmf1 = cmf_s[lr0 + 8];
        __half* e0p = g_Eh + ((size_t)(b * LCC + i0 + lr0)) * LQQ;
        __half* e1p = e0p + 8 * LQQ;
#pragma unroll
        for (int c = 0; c < 8; c++) {
            int col = wn * 64 + c * 8 + 2 * q4;
            float qw0 = qw2_s[col], qw1 = qw2_s[col + 1];
            float qf0 = qmf_s[col], qf1 = qmf_s[col + 1];
            float s0 = acc[a][c][0] + cwv0 + qw0;
            float s1 = acc[a][c][1] + cwv0 + qw1;
            float s2 = acc[a][c][2] + cwv1 + qw0;
            float s3 = acc[a][c][3] + cwv1 + qw1;
            __half h0 = __float2half(__expf(s0));
            __half h1 = __float2half(__expf(s1));
            __half h2 = __float2half(__expf(s2));
            __half h3 = __float2half(__expf(s3));
            *(__half2*)(e0p + col) = __halves2half2(h0, h1);
            *(__half2*)(e1p + col) = __halves2half2(h2, h3);
            float e0 = __half2float(h0), e1 = __half2float(h1);
            float e2 = __half2float(h2), e3 = __half2float(h3);
            z1a[a][0] += qf0 * e0 + qf1 * e1;
            z1a[a][1] += qf0 * e2 + qf1 * e3;
            z2a[c][0] += cmf0 * e0 + cmf1 * e2;
            z2a[c][1] += cmf0 * e1 + cmf1 * e3;
        }
    }
#pragma unroll
    for (int a = 0; a < 2; a++)
#pragma unroll
        for (int h = 0; h < 2; h++) {
            float v = z1a[a][h];
            v += __shfl_xor_sync(~0u, v, 1);
            v += __shfl_xor_sync(~0u, v, 2);
            if (q4 == 0) z1s[wm * 32 + a * 16 + g + 8 * h][wn] = v;
        }
#pragma unroll
    for (int c = 0; c < 8; c++)
#pragma unroll
        for (int s = 0; s < 2; s++) {
            float v = z2a[c][s];
            v += __shfl_xor_sync(~0u, v, 4);
            v += __shfl_xor_sync(~0u, v, 8);
            v += __shfl_xor_sync(~0u, v, 16);
            if (g == 0) z2s[wn * 64 + c * 8 + 2 * q4 + s][wm] = v;
        }
    __syncthreads();
    if (t < 128) {
        g_z1inv[b * LCC + i0 + t] = 1.f / (z1s[t][0] + z1s[t][1]);
        g_z2p[blockIdx.x][b * LQQ + t] = z2s[t][0] + z2s[t][1] + z2s[t][2] + z2s[t][3];
    }
}

// ---------------------------------------------------------------------------
// K3: T[j,d] = qmf[j]/z2[j] * sum_i cmf[i]*E[i,j]*c[i,d]  -> fp16 g_Tm
// N-split over d halves: grid (2, BB). M=128 j, N=64 d, K=1024 i.
// cp.async double-buffered (64-i chunks). cmf applied by scaling A-frags.
// ---------------------------------------------------------------------------
#define EBUFB (64 * LDH * 2)    // bytes per E buffer
#define CBUFB (64 * LDHC * 2)   // bytes per c buffer
__global__ __launch_bounds__(256) void k3_T(const int* __restrict__ c_mask,
                                            const int* __restrict__ q_mask) {
    int b = blockIdx.y, d0 = blockIdx.x * 64;
    extern __shared__ __half s3[];
    __half* E_s   = s3;                         // 2 x 64 x LDH
    __half* c_s   = s3 + 2 * 64 * LDH;          // 2 x 64 x LDHC
    __half* cmf_s = s3 + 2 * 64 * LDH + 2 * 64 * LDHC;  // 1024
    float*  f_s   = (float*)(cmf_s + 1024);     // 128
    int t = threadIdx.x, lane = t & 31, wp = t >> 5, wm = wp >> 1, wn = wp & 1;

    unsigned Ebase = sm_addr(E_s);
    unsigned Cbase = sm_addr(c_s);
    // prefetch chunk 0
    {
        const char* gE = (const char*)(g_Eh + ((size_t)b * LCC) * LQQ);
        const char* gC = (const char*)(g_ch + ((size_t)b * LCC) * DDIM + d0);
#pragma unroll
        for (int l = 0; l < 4; l++) {
            int u = t + l * 256, row = u >> 4, c16 = u & 15;
            cp_async16(Ebase + (row * LDH + c16 * 8) * 2, gE + ((size_t)row * LQQ + c16 * 8) * 2);
        }
#pragma unroll
        for (int l = 0; l < 2; l++) {
            int u = t + l * 256, row = u >> 3, c8 = u & 7;
            cp_async16(Cbase + (row * LDHC + c8 * 8) * 2, gC + ((size_t)row * DDIM + c8 * 8) * 2);
        }
        cp_commit();
    }
    // cmf halfs for all 1024 i; f_s = qmf/z2 per j
#pragma unroll
    for (int l = 0; l < 4; l++) {
        int i = t + l * 256;
        cmf_s[i] = __float2half(c_mask[b * LCC + i] ? 0.f : 1.f);
    }
    if (t < 128) {
        float z2 = 0.f;
#pragma unroll
        for (int s = 0; s < 8; s++) z2 += g_z2p[s][b * LQQ + t];
        f_s[t] = q_mask[b * LQQ + t] ? 0.f : (1.f / z2);
    }

    float acc[2][4][4];
#pragma unroll
    for (int a = 0; a < 2; a++)
#pragma unroll
        for (int c = 0; c < 4; c++)
#pragma unroll
            for (int k = 0; k < 4; k++) acc[a][c][k] = 0.f;

    unsigned aB = Ebase + (((lane & 7) + 8 * ((lane >> 4) & 1)) * LDH
                           + wm * 32 + 8 * ((lane >> 3) & 1)) * 2;
    unsigned bB = Cbase + (((lane & 7) + 8 * ((lane >> 3) & 1)) * LDHC
                           + wn * 32 + 8 * ((lane >> 4) & 1)) * 2;

    for (int kc = 0; kc < 16; kc++) {
        int buf = kc & 1;
        if (kc + 1 < 16) {
            int nxt = buf ^ 1;
            const char* gE = (const char*)(g_Eh + ((size_t)(b * LCC + (kc + 1) * 64)) * LQQ);
            const char* gC = (const char*)(g_ch + ((size_t)(b * LCC + (kc + 1) * 64)) * DDIM + d0);
#pragma unroll
            for (int l = 0; l < 4; l++) {
                int u = t + l * 256, row = u >> 4, c16 = u & 15;
                cp_async16(Ebase + nxt * EBUFB + (row * LDH + c16 * 8) * 2,
                           gE + ((size_t)row * LQQ + c16 * 8) * 2);
            }
#pragma unroll
            for (int l = 0; l < 2; l++) {
                int u = t + l * 256, row = u >> 3, c8 = u & 7;
                cp_async16(Cbase + nxt * CBUFB + (row * LDHC + c8 * 8) * 2,
                           gC + ((size_t)row * DDIM + c8 * 8) * 2);
            }
            cp_commit();
            cp_wait<1>();
        } else {
            cp_wait<0>();
        }
        __syncthreads();
#pragma unroll
        for (int ks = 0; ks < 4; ks++) {
            int ibase = kc * 64 + ks * 16;
            __half2 cm_lo = *(__half2*)&cmf_s[ibase + (lane & 3) * 2];
            __half2 cm_hi = *(__half2*)&cmf_s[ibase + 8 + (lane & 3) * 2];
            unsigned A[2][4];
            ldsm_x4t(aB + buf * EBUFB + ks * (16 * LDH * 2),      A[0][0], A[0][1], A[0][2], A[0][3]);
            ldsm_x4t(aB + buf * EBUFB + ks * (16 * LDH * 2) + 32, A[1][0], A[1][1], A[1][2], A[1][3]);
#pragma unroll
            for (int a = 0; a < 2; a++) {
                A[a][0] = hmul2u(A[a][0], cm_lo);
                A[a][1] = hmul2u(A[a][1], cm_lo);
                A[a][2] = hmul2u(A[a][2], cm_hi);
                A[a][3] = hmul2u(A[a][3], cm_hi);
            }
            unsigned Bf[4][2];
#pragma unroll
            for (int np = 0; np < 2; np++) {
                unsigned r0, r1, r2, r3;
                ldsm_x4t(bB + buf * CBUFB + ks * (16 * LDHC * 2) + np * 32, r0, r1, r2, r3);
                Bf[2 * np][0] = r0; Bf[2 * np][1] = r1;
                Bf[2 * np + 1][0] = r2; Bf[2 * np + 1][1] = r3;
            }
#pragma unroll
            for (int a = 0; a < 2; a++)
#pragma unroll
                for (int c = 0; c < 4; c++)
                    mma16816(acc[a][c][0], acc[a][c][1], acc[a][c][2], acc[a][c][3],
                             A[a][0], A[a][1], A[a][2], A[a][3], Bf[c][0], Bf[c][1]);
        }
        __syncthreads();
    }

    int g = lane >> 2, q4 = lane & 3;
#pragma unroll
    for (int a = 0; a < 2; a++) {
        int j0 = wm * 32 + a * 16 + g;
        float f0 = f_s[j0], f1 = f_s[j0 + 8];
        __half* o0 = g_Tm + ((size_t)(b * LQQ + j0)) * DDIM + d0;
        __half* o1 = o0 + 8 * DDIM;
#pragma unroll
        for (int c = 0; c < 4; c++) {
            int col = wn * 32 + c * 8 + 2 * q4;
            *(__half2*)(o0 + col) = __floats2half2_rn(acc[a][c][0] * f0, acc[a][c][1] * f0);
            *(__half2*)(o1 + col) = __floats2half2_rn(acc[a][c][2] * f1, acc[a][c][3] * f1);
        }
    }
}

// ---------------------------------------------------------------------------
// K4: fused dual GEMM A = (E·qmh)/z1, Batt = (E·Tm)/z1, epilogue writes
// out = [c, A, c*A, c*Batt].  N-SPLIT: grid (16, BB); bx&1 = d-half,
// bx>>1 = i-tile.  M=128 i, N=64 d, K=128 j.  2 CTAs/SM for latency hiding.
// ---------------------------------------------------------------------------
__global__ __launch_bounds__(256, 2) void k4_out(const float* __restrict__ c_rep,
                                                 float* __restrict__ out) {
    int b = blockIdx.y;
    int i0 = (blockIdx.x >> 1) * 128;
    int d0 = (blockIdx.x & 1) * 64;
    extern __shared__ __half sm4[];
    __half* E_s = sm4;                   // [128][LDH]   rows i, cols j (A)
    __half* q_s = sm4 + 128 * LDH;       // [128][LDHC]  rows j, d-half (B)
    __half* t_s = q_s + 128 * LDHC;      // [128][LDHC]  rows j, d-half (B)
    int t = threadIdx.x, lane = t & 31, wp = t >> 5, wm = wp >> 1, wn = wp & 1;
    const uint4* gE = (const uint4*)(g_Eh + ((size_t)(b * LCC + i0)) * LQQ);
    const __half* gQ = g_qmh + (size_t)b * LQQ * DDIM + d0;
    const __half* gT = g_Tm + (size_t)b * LQQ * DDIM + d0;
#pragma unroll
    for (int l = 0; l < 8; l++) {
        int u = t + l * 256, row = u >> 4, c16 = u & 15;
        *(uint4*)&E_s[row * LDH + c16 * 8] = gE[u];
    }
#pragma unroll
    for (int l = 0; l < 4; l++) {
        int u = t + l * 256, row = u >> 3, c8 = u & 7;
        *(uint4*)&q_s[row * LDHC + c8 * 8] = *(const uint4*)(gQ + (size_t)row * DDIM + c8 * 8);
        *(uint4*)&t_s[row * LDHC + c8 * 8] = *(const uint4*)(gT + (size_t)row * DDIM + c8 * 8);
    }
    __syncthreads();

    float accA[2][4][4], accB[2][4][4];
#pragma unroll
    for (int a = 0; a < 2; a++)
#pragma unroll
        for (int c = 0; c < 4; c++)
#pragma unroll
            for (int k = 0; k < 4; k++) { accA[a][c][k] = 0.f; accB[a][c][k] = 0.f; }

    unsigned aB = sm_addr(&E_s[(wm * 32 + (lane & 15)) * LDH + 8 * (lane >> 4)]);
    unsigned qB = sm_addr(&q_s[((lane & 7) + 8 * ((lane >> 3) & 1)) * LDHC
                               + wn * 32 + 8 * ((lane >> 4) & 1)]);
    unsigned tB = sm_addr(&t_s[((lane & 7) + 8 * ((lane >> 3) & 1)) * LDHC
                               + wn * 32 + 8 * ((lane >> 4) & 1)]);
#pragma unroll
    for (int ks = 0; ks < 8; ks++) {
        unsigned A[2][4];
        ldsm_x4(aB + ks * 32,                A[0][0], A[0][1], A[0][2], A[0][3]);
        ldsm_x4(aB + 16 * LDH * 2 + ks * 32, A[1][0], A[1][1], A[1][2], A[1][3]);
#pragma unroll
        for (int np = 0; np < 2; np++) {
            unsigned r0, r1, r2, r3;
            ldsm_x4t(qB + ks * (16 * LDHC * 2) + np * 32, r0, r1, r2, r3);
#pragma unroll
            for (int a = 0; a < 2; a++) {
                mma16816(accA[a][2 * np][0], accA[a][2 * np][1], accA[a][2 * np][2], accA[a][2 * np][3],
                         A[a][0], A[a][1], A[a][2], A[a][3], r0, r1);
                mma16816(accA[a][2 * np + 1][0], accA[a][2 * np + 1][1], accA[a][2 * np + 1][2], accA[a][2 * np + 1][3],
                         A[a][0], A[a][1], A[a][2], A[a][3], r2, r3);
            }
            ldsm_x4t(tB + ks * (16 * LDHC * 2) + np * 32, r0, r1, r2, r3);
#pragma unroll
            for (int a = 0; a < 2; a++) {
                mma16816(accB[a][2 * np][0], accB[a][2 * np][1], accB[a][2 * np][2], accB[a][2 * np][3],
                         A[a][0], A[a][1], A[a][2], A[a][3], r0, r1);
                mma16816(accB[a][2 * np + 1][0], accB[a][2 * np + 1][1], accB[a][2 * np + 1][2], accB[a][2 * np + 1][3],
                         A[a][0], A[a][1], A[a][2], A[a][3], r2, r3);
            }
        }
    }

    int g = lane >> 2, q4 = lane & 3;
#pragma unroll
    for (int a = 0; a < 2; a++) {
        int lr0 = wm * 32 + a * 16 + g;
        size_t gr0 = (size_t)(b * LCC + i0 + lr0);
        size_t gr1 = gr0 + 8;
        float z0 = g_z1inv[gr0], z1v = g_z1inv[gr1];
        const float* cp0 = c_rep + gr0 * DDIM + d0;
        const float* cp1 = c_rep + gr1 * DDIM + d0;
        float* o0 = out + gr0 * (4 * DDIM) + d0;
        float* o1 = out + gr1 * (4 * DDIM) + d0;
#pragma unroll
        for (int c = 0; c < 4; c++) {
            int col = wn * 32 + c * 8 + 2 * q4;
            float2 cv0 = *(const float2*)(cp0 + col);
            float2 cv1 = *(const float2*)(cp1 + col);
            float2 av0 = make_float2(accA[a][c][0] * z0, accA[a][c][1] * z0);
            float2 av1 = make_float2(accA[a][c][2] * z1v, accA[a][c][3] * z1v);
            float2 bv0 = make_float2(accB[a][c][0] * z0, accB[a][c][1] * z0);
            float2 bv1 = make_float2(accB[a][c][2] * z1v, accB[a][c][3] * z1v);
            *(float2*)(o0 + col) = cv0;
            *(float2*)(o1 + col) = cv1;
            *(float2*)(o0 + DDIM + col) = av0;
            *(float2*)(o1 + DDIM + col) = av1;
            *(float2*)(o0 + 2 * DDIM + col) = make_float2(cv0.x * av0.x, cv0.y * av0.y);
            *(float2*)(o1 + 2 * DDIM + col) = make_float2(cv1.x * av1.x, cv1.y * av1.y);
            *(float2*)(o0 + 3 * DDIM + col) = make_float2(cv0.x * bv0.x, cv0.y * bv0.y);
            *(float2*)(o1 + 3 * DDIM + col) = make_float2(cv1.x * bv1.x, cv1.y * bv1.y);
        }
    }
}

// ---------------------------------------------------------------------------
extern "C" void kernel_launch(void* const* d_in, const int* in_sizes, int n_in,
                              void* d_out, int out_size) {
    const float* c_rep  = (const float*)d_in[0];
    const float* q_rep  = (const float*)d_in[1];
    const int*   c_mask = (const int*)d_in[2];
    const int*   q_mask = (const int*)d_in[3];
    const float* w      = (const float*)d_in[4];
    float* out = (float*)d_out;

    k0_prep<<<(BB * LCC + BB * LQQ) / 8, 256>>>(c_rep, q_rep, q_mask, w);
    {
        int smem = 2 * 128 * LDH * 2;  // 69632
        cudaFuncSetAttribute(k2_SE, cudaFuncAttributeMaxDynamicSharedMemorySize, smem);
        dim3 gr(8, BB);
        k2_SE<<<gr, 256, smem>>>(c_mask, q_mask);
    }
    {
        int smem = 2 * EBUFB + 2 * CBUFB + 1024 * 2 + 128 * 4;  // 55808
        cudaFuncSetAttribute(k3_T, cudaFuncAttributeMaxDynamicSharedMemorySize, smem);
        dim3 gr(2, BB);
        k3_T<<<gr, 256, smem>>>(c_mask, q_mask);
    }
    {
        int smem = (128 * LDH + 2 * 128 * LDHC) * 2;  // 71680
        cudaFuncSetAttribute(k4_out, cudaFuncAttributeMaxDynamicSharedMemorySize, smem);
        dim3 gr(16, BB);
        k4_out<<<gr, 256, smem>>>(c_rep, out);
    }
}

// round 6
// speedup vs baseline: 4.4750x; 1.0336x over previous
#include <cuda_runtime.h>
#include <cuda_fp16.h>
#include <math.h>

#define BB 64
#define LCC 1024
#define LQQ 128
#define DDIM 128
#define LDH 136        // smem row stride in halfs (272B)
#define LDHC 72        // half-width slab row stride in halfs (144B)
#define LDS4 72        // k4 staging stride in floats

// ---- device scratch (allocation-free) ----
__device__ __half g_ch [(size_t)BB * LCC * DDIM];  // fp16(c)
__device__ __half g_qwh[BB * LQQ * DDIM];          // fp16(q * w3)
__device__ __half g_qmh[BB * LQQ * DDIM];          // fp16(q * qmf)
__device__ __half g_Eh [(size_t)BB * LCC * LQQ];   // fp16(exp(S))
__device__ __half g_Tm [BB * LQQ * DDIM];          // fp16(T * qmf)
__device__ float  g_cw1[BB * LCC];
__device__ float  g_qw2[BB * LQQ];
__device__ float  g_z1inv[BB * LCC];
__device__ float  g_z2p[8][BB * LQQ];              // col-sum partials per i-tile

// ---- mma / ldmatrix / cp.async helpers ----
__device__ __forceinline__ unsigned sm_addr(const void* p) {
    return (unsigned)__cvta_generic_to_shared(p);
}
__device__ __forceinline__ void ldsm_x4(unsigned a, unsigned& r0, unsigned& r1,
                                        unsigned& r2, unsigned& r3) {
    asm volatile("ldmatrix.sync.aligned.m8n8.x4.shared.b16 {%0,%1,%2,%3}, [%4];"
                 : "=r"(r0), "=r"(r1), "=r"(r2), "=r"(r3) : "r"(a));
}
__device__ __forceinline__ void ldsm_x4t(unsigned a, unsigned& r0, unsigned& r1,
                                         unsigned& r2, unsigned& r3) {
    asm volatile("ldmatrix.sync.aligned.m8n8.x4.trans.shared.b16 {%0,%1,%2,%3}, [%4];"
                 : "=r"(r0), "=r"(r1), "=r"(r2), "=r"(r3) : "r"(a));
}
__device__ __forceinline__ void mma16816(float& c0, float& c1, float& c2, float& c3,
                                         unsigned a0, unsigned a1, unsigned a2, unsigned a3,
                                         unsigned b0, unsigned b1) {
    asm volatile(
        "mma.sync.aligned.m16n8k16.row.col.f32.f16.f16.f32 "
        "{%0,%1,%2,%3}, {%4,%5,%6,%7}, {%8,%9}, {%0,%1,%2,%3};"
        : "+f"(c0), "+f"(c1), "+f"(c2), "+f"(c3)
        : "r"(a0), "r"(a1), "r"(a2), "r"(a3), "r"(b0), "r"(b1));
}
__device__ __forceinline__ void cp_async16(unsigned saddr, const void* g) {
    asm volatile("cp.async.cg.shared.global [%0], [%1], 16;" :: "r"(saddr), "l"(g));
}
__device__ __forceinline__ void cp_commit() {
    asm volatile("cp.async.commit_group;");
}
template <int N> __device__ __forceinline__ void cp_wait() {
    asm volatile("cp.async.wait_group %0;" :: "n"(N));
}
__device__ __forceinline__ unsigned hmul2u(unsigned a, __half2 s) {
    __half2 r = __hmul2(*(__half2*)&a, s);
    return *(unsigned*)&r;
}

// ---------------------------------------------------------------------------
// K0: warp per row. cw1/qw2 fp32 dots; fp16 conversions: c plain, q*w3, q*qmf.
// ---------------------------------------------------------------------------
__global__ __launch_bounds__(256) void k0_prep(const float* __restrict__ c_rep,
                                               const float* __restrict__ q_rep,
                                               const int* __restrict__ q_mask,
                                               const float* __restrict__ w) {
    int gw   = (blockIdx.x * 256 + threadIdx.x) >> 5;
    int lane = threadIdx.x & 31;
    const int NC = BB * LCC;
    if (gw < NC) {
        float4 cv = *(const float4*)(c_rep + (size_t)gw * DDIM + lane * 4);
        float4 w1 = *(const float4*)(w + lane * 4);
        float s = cv.x * w1.x + cv.y * w1.y + cv.z * w1.z + cv.w * w1.w;
#pragma unroll
        for (int o = 16; o > 0; o >>= 1) s += __shfl_xor_sync(~0u, s, o);
        if (lane == 0) g_cw1[gw] = s;
        __half2 a0 = __floats2half2_rn(cv.x, cv.y);
        __half2 a1 = __floats2half2_rn(cv.z, cv.w);
        uint2 u; u.x = *(unsigned*)&a0; u.y = *(unsigned*)&a1;
        *(uint2*)(g_ch + (size_t)gw * DDIM + lane * 4) = u;
    } else if (gw < NC + BB * LQQ) {
        int r = gw - NC;
        float4 qv = *(const float4*)(q_rep + (size_t)r * DDIM + lane * 4);
        float4 w2 = *(const float4*)(w + DDIM + lane * 4);
        float4 w3 = *(const float4*)(w + 2 * DDIM + lane * 4);
        float s = qv.x * w2.x + qv.y * w2.y + qv.z * w2.z + qv.w * w2.w;
#pragma unroll
        for (int o = 16; o > 0; o >>= 1) s += __shfl_xor_sync(~0u, s, o);
        if (lane == 0) g_qw2[r] = s;
        __half2 a0 = __floats2half2_rn(qv.x * w3.x, qv.y * w3.y);
        __half2 a1 = __floats2half2_rn(qv.z * w3.z, qv.w * w3.w);
        uint2 u; u.x = *(unsigned*)&a0; u.y = *(unsigned*)&a1;
        *(uint2*)(g_qwh + (size_t)r * DDIM + lane * 4) = u;
        float mf = q_mask[r] ? 0.f : 1.f;
        __half2 m0 = __floats2half2_rn(qv.x * mf, qv.y * mf);
        __half2 m1 = __floats2half2_rn(qv.z * mf, qv.w * mf);
        uint2 v; v.x = *(unsigned*)&m0; v.y = *(unsigned*)&m1;
        *(uint2*)(g_qmh + (size_t)r * DDIM + lane * 4) = v;
    }
}

// ---------------------------------------------------------------------------
// K2: S = cw1 + qw2 + c·(q*w3)^T  (M=128 i, N=128 j, K=128 d), E=exp(S) fp16,
// z1inv finalized, z2 partials staged. Warps 4(m)x2(n), warp tile 32x64.
// ---------------------------------------------------------------------------
__global__ __launch_bounds__(256) void k2_SE(const int* __restrict__ c_mask,
                                             const int* __restrict__ q_mask) {
    int b = blockIdx.y, i0 = blockIdx.x * 128;
    extern __shared__ __half sm2[];
    __half* cw_s = sm2;                // [128][LDH]  A: rows i, cols d
    __half* q_s  = sm2 + 128 * LDH;    // [128][LDH]  B: rows j, cols d
    __shared__ float z1s[128][2];
    __shared__ float z2s[128][4];
    __shared__ float qmf_s[128], cmf_s[128];
    __shared__ float cw1_s[128], qw2_s[128];
    int t = threadIdx.x, lane = t & 31, wp = t >> 5, wm = wp >> 1, wn = wp & 1;
    if (t < 128) {
        qmf_s[t] = q_mask[b * LQQ + t] ? 0.f : 1.f;
        cmf_s[t] = c_mask[b * LCC + i0 + t] ? 0.f : 1.f;
        cw1_s[t] = g_cw1[b * LCC + i0 + t];
        qw2_s[t] = g_qw2[b * LQQ + t];
    }
    const uint4* gc = (const uint4*)(g_ch + ((size_t)(b * LCC + i0)) * DDIM);
    const uint4* gq = (const uint4*)(g_qwh + (size_t)b * LQQ * DDIM);
#pragma unroll
    for (int l = 0; l < 8; l++) {
        int u = t + l * 256, row = u >> 4, c16 = u & 15;
        *(uint4*)&cw_s[row * LDH + c16 * 8] = gc[u];
        *(uint4*)&q_s [row * LDH + c16 * 8] = gq[u];
    }
    __syncthreads();

    float acc[2][8][4];
#pragma unroll
    for (int a = 0; a < 2; a++)
#pragma unroll
        for (int c = 0; c < 8; c++)
#pragma unroll
            for (int k = 0; k < 4; k++) acc[a][c][k] = 0.f;

    unsigned aB = sm_addr(&cw_s[(wm * 32 + (lane & 15)) * LDH + 8 * (lane >> 4)]);
    unsigned bB = sm_addr(&q_s[(wn * 64 + 8 * ((lane >> 4) & 1) + (lane & 7)) * LDH
                               + 8 * ((lane >> 3) & 1)]);
#pragma unroll
    for (int ks = 0; ks < 8; ks++) {
        unsigned A[2][4];
        ldsm_x4(aB + ks * 32,                 A[0][0], A[0][1], A[0][2], A[0][3]);
        ldsm_x4(aB + 16 * LDH * 2 + ks * 32,  A[1][0], A[1][1], A[1][2], A[1][3]);
        unsigned Bf[8][2];
#pragma unroll
        for (int np = 0; np < 4; np++) {
            unsigned r0, r1, r2, r3;
            ldsm_x4(bB + np * (16 * LDH * 2) + ks * 32, r0, r1, r2, r3);
            Bf[2 * np][0] = r0; Bf[2 * np][1] = r1;
            Bf[2 * np + 1][0] = r2; Bf[2 * np + 1][1] = r3;
        }
#pragma unroll
        for (int a = 0; a < 2; a++)
#pragma unroll
            for (int c = 0; c < 8; c++)
                mma16816(acc[a][c][0], acc[a][c][1], acc[a][c][2], acc[a][c][3],
                         A[a][0], A[a][1], A[a][2], A[a][3], Bf[c][0], Bf[c][1]);
    }

    // epilogue: add rank-1 terms, exp, store E, accumulate z1/z2
    int g = lane >> 2, q4 = lane & 3;
    float z1a[2][2] = {{0.f, 0.f}, {0.f, 0.f}};
    float z2a[8][2];
#pragma unroll
    for (int c = 0; c < 8; c++) { z2a[c][0] = 0.f; z2a[c][1] = 0.f; }
#pragma unroll
    for (int a = 0; a < 2; a++) {
        int lr0 = wm * 32 + a * 16 + g;
        float cwv0 = cw1_s[lr0], cwv1 = cw1_s[lr0 + 8];
        float cmf0 = cmf_s[lr0], cmf1 = cmf_s[lr0 + 8];
        __half* e0p = g_Eh + ((size_t)(b * LCC + i0 + lr0)) * LQQ;
        __half* e1p = e0p + 8 * LQQ;
#pragma unroll
        for (int c = 0; c < 8; c++) {
            int col = wn * 64 + c * 8 + 2 * q4;
            float qw0 = qw2_s[col], qw1 = qw2_s[col + 1];
            float qf0 = qmf_s[col], qf1 = qmf_s[col + 1];
            float s0 = acc[a][c][0] + cwv0 + qw0;
            float s1 = acc[a][c][1] + cwv0 + qw1;
            float s2 = acc[a][c][2] + cwv1 + qw0;
            float s3 = acc[a][c][3] + cwv1 + qw1;
            __half h0 = __float2half(__expf(s0));
            __half h1 = __float2half(__expf(s1));
            __half h2 = __float2half(__expf(s2));
            __half h3 = __float2half(__expf(s3));
            *(__half2*)(e0p + col) = __halves2half2(h0, h1);
            *(__half2*)(e1p + col) = __halves2half2(h2, h3);
            float e0 = __half2float(h0), e1 = __half2float(h1);
            float e2 = __half2float(h2), e3 = __half2float(h3);
            z1a[a][0] += qf0 * e0 + qf1 * e1;
            z1a[a][1] += qf0 * e2 + qf1 * e3;
            z2a[c][0] += cmf0 * e0 + cmf1 * e2;
            z2a[c][1] += cmf0 * e1 + cmf1 * e3;
        }
    }
#pragma unroll
    for (int a = 0; a < 2; a++)
#pragma unroll
        for (int h = 0; h < 2; h++) {
            float v = z1a[a][h];
            v += __shfl_xor_sync(~0u, v, 1);
            v += __shfl_xor_sync(~0u, v, 2);
            if (q4 == 0) z1s[wm * 32 + a * 16 + g + 8 * h][wn] = v;
        }
#pragma unroll
    for (int c = 0; c < 8; c++)
#pragma unroll
        for (int s = 0; s < 2; s++) {
            float v = z2a[c][s];
            v += __shfl_xor_sync(~0u, v, 4);
            v += __shfl_xor_sync(~0u, v, 8);
            v += __shfl_xor_sync(~0u, v, 16);
            if (g == 0) z2s[wn * 64 + c * 8 + 2 * q4 + s][wm] = v;
        }
    __syncthreads();
    if (t < 128) {
        g_z1inv[b * LCC + i0 + t] = 1.f / (z1s[t][0] + z1s[t][1]);
        g_z2p[blockIdx.x][b * LQQ + t] = z2s[t][0] + z2s[t][1] + z2s[t][2] + z2s[t][3];
    }
}

// ---------------------------------------------------------------------------
// K3: T[j,d] = qmf[j]/z2[j] * sum_i cmf[i]*E[i,j]*c[i,d]  -> fp16 g_Tm
// N-split over d halves: grid (2, BB). M=128 j, N=64 d, K=1024 i.
// cp.async double-buffered (64-i chunks). cmf applied by scaling A-frags.
// ---------------------------------------------------------------------------
#define EBUFB (64 * LDH * 2)    // bytes per E buffer
#define CBUFB (64 * LDHC * 2)   // bytes per c buffer
__global__ __launch_bounds__(256) void k3_T(const int* __restrict__ c_mask,
                                            const int* __restrict__ q_mask) {
    int b = blockIdx.y, d0 = blockIdx.x * 64;
    extern __shared__ __half s3[];
    __half* E_s   = s3;                         // 2 x 64 x LDH
    __half* c_s   = s3 + 2 * 64 * LDH;          // 2 x 64 x LDHC
    __half* cmf_s = s3 + 2 * 64 * LDH + 2 * 64 * LDHC;  // 1024
    float*  f_s   = (float*)(cmf_s + 1024);     // 128
    int t = threadIdx.x, lane = t & 31, wp = t >> 5, wm = wp >> 1, wn = wp & 1;

    unsigned Ebase = sm_addr(E_s);
    unsigned Cbase = sm_addr(c_s);
    // prefetch chunk 0
    {
        const char* gE = (const char*)(g_Eh + ((size_t)b * LCC) * LQQ);
        const char* gC = (const char*)(g_ch + ((size_t)b * LCC) * DDIM + d0);
#pragma unroll
        for (int l = 0; l < 4; l++) {
            int u = t + l * 256, row = u >> 4, c16 = u & 15;
            cp_async16(Ebase + (row * LDH + c16 * 8) * 2, gE + ((size_t)row * LQQ + c16 * 8) * 2);
        }
#pragma unroll
        for (int l = 0; l < 2; l++) {
            int u = t + l * 256, row = u >> 3, c8 = u & 7;
            cp_async16(Cbase + (row * LDHC + c8 * 8) * 2, gC + ((size_t)row * DDIM + c8 * 8) * 2);
        }
        cp_commit();
    }
    // cmf halfs for all 1024 i; f_s = qmf/z2 per j
#pragma unroll
    for (int l = 0; l < 4; l++) {
        int i = t + l * 256;
        cmf_s[i] = __float2half(c_mask[b * LCC + i] ? 0.f : 1.f);
    }
    if (t < 128) {
        float z2 = 0.f;
#pragma unroll
        for (int s = 0; s < 8; s++) z2 += g_z2p[s][b * LQQ + t];
        f_s[t] = q_mask[b * LQQ + t] ? 0.f : (1.f / z2);
    }

    float acc[2][4][4];
#pragma unroll
    for (int a = 0; a < 2; a++)
#pragma unroll
        for (int c = 0; c < 4; c++)
#pragma unroll
            for (int k = 0; k < 4; k++) acc[a][c][k] = 0.f;

    unsigned aB = Ebase + (((lane & 7) + 8 * ((lane >> 4) & 1)) * LDH
                           + wm * 32 + 8 * ((lane >> 3) & 1)) * 2;
    unsigned bB = Cbase + (((lane & 7) + 8 * ((lane >> 3) & 1)) * LDHC
                           + wn * 32 + 8 * ((lane >> 4) & 1)) * 2;

    for (int kc = 0; kc < 16; kc++) {
        int buf = kc & 1;
        if (kc + 1 < 16) {
            int nxt = buf ^ 1;
            const char* gE = (const char*)(g_Eh + ((size_t)(b * LCC + (kc + 1) * 64)) * LQQ);
            const char* gC = (const char*)(g_ch + ((size_t)(b * LCC + (kc + 1) * 64)) * DDIM + d0);
#pragma unroll
            for (int l = 0; l < 4; l++) {
                int u = t + l * 256, row = u >> 4, c16 = u & 15;
                cp_async16(Ebase + nxt * EBUFB + (row * LDH + c16 * 8) * 2,
                           gE + ((size_t)row * LQQ + c16 * 8) * 2);
            }
#pragma unroll
            for (int l = 0; l < 2; l++) {
                int u = t + l * 256, row = u >> 3, c8 = u & 7;
                cp_async16(Cbase + nxt * CBUFB + (row * LDHC + c8 * 8) * 2,
                           gC + ((size_t)row * DDIM + c8 * 8) * 2);
            }
            cp_commit();
            cp_wait<1>();
        } else {
            cp_wait<0>();
        }
        __syncthreads();
#pragma unroll
        for (int ks = 0; ks < 4; ks++) {
            int ibase = kc * 64 + ks * 16;
            __half2 cm_lo = *(__half2*)&cmf_s[ibase + (lane & 3) * 2];
            __half2 cm_hi = *(__half2*)&cmf_s[ibase + 8 + (lane & 3) * 2];
            unsigned A[2][4];
            ldsm_x4t(aB + buf * EBUFB + ks * (16 * LDH * 2),      A[0][0], A[0][1], A[0][2], A[0][3]);
            ldsm_x4t(aB + buf * EBUFB + ks * (16 * LDH * 2) + 32, A[1][0], A[1][1], A[1][2], A[1][3]);
#pragma unroll
            for (int a = 0; a < 2; a++) {
                A[a][0] = hmul2u(A[a][0], cm_lo);
                A[a][1] = hmul2u(A[a][1], cm_lo);
                A[a][2] = hmul2u(A[a][2], cm_hi);
                A[a][3] = hmul2u(A[a][3], cm_hi);
            }
            unsigned Bf[4][2];
#pragma unroll
            for (int np = 0; np < 2; np++) {
                unsigned r0, r1, r2, r3;
                ldsm_x4t(bB + buf * CBUFB + ks * (16 * LDHC * 2) + np * 32, r0, r1, r2, r3);
                Bf[2 * np][0] = r0; Bf[2 * np][1] = r1;
                Bf[2 * np + 1][0] = r2; Bf[2 * np + 1][1] = r3;
            }
#pragma unroll
            for (int a = 0; a < 2; a++)
#pragma unroll
                for (int c = 0; c < 4; c++)
                    mma16816(acc[a][c][0], acc[a][c][1], acc[a][c][2], acc[a][c][3],
                             A[a][0], A[a][1], A[a][2], A[a][3], Bf[c][0], Bf[c][1]);
        }
        __syncthreads();
    }

    int g = lane >> 2, q4 = lane & 3;
#pragma unroll
    for (int a = 0; a < 2; a++) {
        int j0 = wm * 32 + a * 16 + g;
        float f0 = f_s[j0], f1 = f_s[j0 + 8];
        __half* o0 = g_Tm + ((size_t)(b * LQQ + j0)) * DDIM + d0;
        __half* o1 = o0 + 8 * DDIM;
#pragma unroll
        for (int c = 0; c < 4; c++) {
            int col = wn * 32 + c * 8 + 2 * q4;
            *(__half2*)(o0 + col) = __floats2half2_rn(acc[a][c][0] * f0, acc[a][c][1] * f0);
            *(__half2*)(o1 + col) = __floats2half2_rn(acc[a][c][2] * f1, acc[a][c][3] * f1);
        }
    }
}

// ---------------------------------------------------------------------------
// K4: fused dual GEMM A = (E·qmh)/z1, Batt = (E·Tm)/z1; smem-staged epilogue
// emits fully-coalesced float4 stores of [c, A, c*A, c*Batt].
// Grid (16, BB): bx&1 = d-half, bx>>1 = i-tile. M=128 i, N=64 d, K=128 j.
// ---------------------------------------------------------------------------
__global__ __launch_bounds__(256, 2) void k4_out(const float* __restrict__ c_rep,
                                                 float* __restrict__ out) {
    int b = blockIdx.y;
    int i0 = (blockIdx.x >> 1) * 128;
    int d0 = (blockIdx.x & 1) * 64;
    extern __shared__ __half sm4[];
    __half* E_s = sm4;                   // [128][LDH]   rows i, cols j (A)
    __half* q_s = sm4 + 128 * LDH;       // [128][LDHC]  rows j, d-half (B)
    __half* t_s = q_s + 128 * LDHC;      // [128][LDHC]  rows j, d-half (B)
    float* Asm = (float*)sm4;            // staging (reused post-MMA): [32][LDS4]
    float* Bsm = Asm + 32 * LDS4;
    int t = threadIdx.x, lane = t & 31, wp = t >> 5, wm = wp >> 1, wn = wp & 1;
    const uint4* gE = (const uint4*)(g_Eh + ((size_t)(b * LCC + i0)) * LQQ);
    const __half* gQ = g_qmh + (size_t)b * LQQ * DDIM + d0;
    const __half* gT = g_Tm + (size_t)b * LQQ * DDIM + d0;
#pragma unroll
    for (int l = 0; l < 8; l++) {
        int u = t + l * 256, row = u >> 4, c16 = u & 15;
        *(uint4*)&E_s[row * LDH + c16 * 8] = gE[u];
    }
#pragma unroll
    for (int l = 0; l < 4; l++) {
        int u = t + l * 256, row = u >> 3, c8 = u & 7;
        *(uint4*)&q_s[row * LDHC + c8 * 8] = *(const uint4*)(gQ + (size_t)row * DDIM + c8 * 8);
        *(uint4*)&t_s[row * LDHC + c8 * 8] = *(const uint4*)(gT + (size_t)row * DDIM + c8 * 8);
    }
    __syncthreads();

    float accA[2][4][4], accB[2][4][4];
#pragma unroll
    for (int a = 0; a < 2; a++)
#pragma unroll
        for (int c = 0; c < 4; c++)
#pragma unroll
            for (int k = 0; k < 4; k++) { accA[a][c][k] = 0.f; accB[a][c][k] = 0.f; }

    unsigned aB = sm_addr(&E_s[(wm * 32 + (lane & 15)) * LDH + 8 * (lane >> 4)]);
    unsigned qB = sm_addr(&q_s[((lane & 7) + 8 * ((lane >> 3) & 1)) * LDHC
                               + wn * 32 + 8 * ((lane >> 4) & 1)]);
    unsigned tB = sm_addr(&t_s[((lane & 7) + 8 * ((lane >> 3) & 1)) * LDHC
                               + wn * 32 + 8 * ((lane >> 4) & 1)]);
#pragma unroll
    for (int ks = 0; ks < 8; ks++) {
        unsigned A[2][4];
        ldsm_x4(aB + ks * 32,                A[0][0], A[0][1], A[0][2], A[0][3]);
        ldsm_x4(aB + 16 * LDH * 2 + ks * 32, A[1][0], A[1][1], A[1][2], A[1][3]);
#pragma unroll
        for (int np = 0; np < 2; np++) {
            unsigned r0, r1, r2, r3;
            ldsm_x4t(qB + ks * (16 * LDHC * 2) + np * 32, r0, r1, r2, r3);
#pragma unroll
            for (int a = 0; a < 2; a++) {
                mma16816(accA[a][2 * np][0], accA[a][2 * np][1], accA[a][2 * np][2], accA[a][2 * np][3],
                         A[a][0], A[a][1], A[a][2], A[a][3], r0, r1);
                mma16816(accA[a][2 * np + 1][0], accA[a][2 * np + 1][1], accA[a][2 * np + 1][2], accA[a][2 * np + 1][3],
                         A[a][0], A[a][1], A[a][2], A[a][3], r2, r3);
            }
            ldsm_x4t(tB + ks * (16 * LDHC * 2) + np * 32, r0, r1, r2, r3);
#pragma unroll
            for (int a = 0; a < 2; a++) {
                mma16816(accB[a][2 * np][0], accB[a][2 * np][1], accB[a][2 * np][2], accB[a][2 * np][3],
                         A[a][0], A[a][1], A[a][2], A[a][3], r0, r1);
                mma16816(accB[a][2 * np + 1][0], accB[a][2 * np + 1][1], accB[a][2 * np + 1][2], accB[a][2 * np + 1][3],
                         A[a][0], A[a][1], A[a][2], A[a][3], r2, r3);
            }
        }
    }

    // z1inv for this thread's own rows
    int g = lane >> 2, q4 = lane & 3;
    float zv[2][2];
#pragma unroll
    for (int a = 0; a < 2; a++) {
        size_t gr = (size_t)(b * LCC + i0 + wm * 32 + a * 16 + g);
        zv[a][0] = g_z1inv[gr];
        zv[a][1] = g_z1inv[gr + 8];
    }
    __syncthreads();   // all warps done reading E_s/q_s/t_s; smem reused below

    // staged epilogue: 4 stages x 32 rows
#pragma unroll
    for (int s = 0; s < 4; s++) {
        if (wm == s) {
#pragma unroll
            for (int a = 0; a < 2; a++) {
                int r0 = a * 16 + g, r1 = r0 + 8;
                float z0 = zv[a][0], z1v = zv[a][1];
#pragma unroll
                for (int c = 0; c < 4; c++) {
                    int col = wn * 32 + c * 8 + 2 * q4;
                    *(float2*)&Asm[r0 * LDS4 + col] = make_float2(accA[a][c][0] * z0, accA[a][c][1] * z0);
                    *(float2*)&Asm[r1 * LDS4 + col] = make_float2(accA[a][c][2] * z1v, accA[a][c][3] * z1v);
                    *(float2*)&Bsm[r0 * LDS4 + col] = make_float2(accB[a][c][0] * z0, accB[a][c][1] * z0);
                    *(float2*)&Bsm[r1 * LDS4 + col] = make_float2(accB[a][c][2] * z1v, accB[a][c][3] * z1v);
                }
            }
        }
        __syncthreads();
#pragma unroll
        for (int it = 0; it < 2; it++) {
            int u = t + it * 256;
            int row = u >> 4, col = (u & 15) * 4;
            size_t gr = (size_t)(b * LCC + i0 + s * 32 + row);
            float4 c4 = *(const float4*)(c_rep + gr * DDIM + d0 + col);
            float4 a4 = *(const float4*)&Asm[row * LDS4 + col];
            float4 b4 = *(const float4*)&Bsm[row * LDS4 + col];
            float* ob = out + gr * (4 * DDIM) + d0 + col;
            *(float4*)ob = c4;
            *(float4*)(ob + DDIM) = a4;
            *(float4*)(ob + 2 * DDIM) = make_float4(c4.x * a4.x, c4.y * a4.y, c4.z * a4.z, c4.w * a4.w);
            *(float4*)(ob + 3 * DDIM) = make_float4(c4.x * b4.x, c4.y * b4.y, c4.z * b4.z, c4.w * b4.w);
        }
        __syncthreads();
    }
}

// ---------------------------------------------------------------------------
extern "C" void kernel_launch(void* const* d_in, const int* in_sizes, int n_in,
                              void* d_out, int out_size) {
    const float* c_rep  = (const float*)d_in[0];
    const float* q_rep  = (const float*)d_in[1];
    const int*   c_mask = (const int*)d_in[2];
    const int*   q_mask = (const int*)d_in[3];
    const float* w      = (const float*)d_in[4];
    float* out = (float*)d_out;

    k0_prep<<<(BB * LCC + BB * LQQ) / 8, 256>>>(c_rep, q_rep, q_mask, w);
    {
        int smem = 2 * 128 * LDH * 2;  // 69632
        cudaFuncSetAttribute(k2_SE, cudaFuncAttributeMaxDynamicSharedMemorySize, smem);
        dim3 gr(8, BB);
        k2_SE<<<gr, 256, smem>>>(c_mask, q_mask);
    }
    {
        int smem = 2 * EBUFB + 2 * CBUFB + 1024 * 2 + 128 * 4;  // 55808
        cudaFuncSetAttribute(k3_T, cudaFuncAttributeMaxDynamicSharedMemorySize, smem);
        dim3 gr(2, BB);
        k3_T<<<gr, 256, smem>>>(c_mask, q_mask);
    }
    {
        int smem = (128 * LDH + 2 * 128 * LDHC) * 2;  // 71680 (>= staging 36.9KB)
        cudaFuncSetAttribute(k4_out, cudaFuncAttributeMaxDynamicSharedMemorySize, smem);
        dim3 gr(16, BB);
        k4_out<<<gr, 256, smem>>>(c_rep, out);
    }
}

// round 7
// speedup vs baseline: 4.8074x; 1.0743x over previous
#include <cuda_runtime.h>
#include <cuda_fp16.h>
#include <math.h>

#define BB 64
#define LCC 1024
#define LQQ 128
#define DDIM 128
#define LDH 136        // smem row stride in halfs (272B)
#define LDHC 72        // half-width slab row stride in halfs (144B)
#define LDS4 72        // k4 staging stride in floats
#define LOG2E 1.4426950408889634f

// ---- device scratch (allocation-free) ----
__device__ __half g_ch [(size_t)BB * LCC * DDIM];  // fp16(c)
__device__ __half g_qwh[BB * LQQ * DDIM];          // fp16(q * w3 * log2e)
__device__ __half g_qmh[BB * LQQ * DDIM];          // fp16(q * qmf)
__device__ __half g_Eh [(size_t)BB * LCC * LQQ];   // fp16(exp(S))
__device__ __half g_Tm [BB * LQQ * DDIM];          // fp16(T * qmf)
__device__ float  g_cw1[BB * LCC];                 // (c·w1) * log2e
__device__ float  g_qw2[BB * LQQ];                 // (q·w2) * log2e
__device__ float  g_z1inv[BB * LCC];
__device__ float  g_z2p[8][BB * LQQ];              // col-sum partials per i-tile

// ---- mma / ldmatrix / cp.async helpers ----
__device__ __forceinline__ unsigned sm_addr(const void* p) {
    return (unsigned)__cvta_generic_to_shared(p);
}
__device__ __forceinline__ void ldsm_x4(unsigned a, unsigned& r0, unsigned& r1,
                                        unsigned& r2, unsigned& r3) {
    asm volatile("ldmatrix.sync.aligned.m8n8.x4.shared.b16 {%0,%1,%2,%3}, [%4];"
                 : "=r"(r0), "=r"(r1), "=r"(r2), "=r"(r3) : "r"(a));
}
__device__ __forceinline__ void ldsm_x4t(unsigned a, unsigned& r0, unsigned& r1,
                                         unsigned& r2, unsigned& r3) {
    asm volatile("ldmatrix.sync.aligned.m8n8.x4.trans.shared.b16 {%0,%1,%2,%3}, [%4];"
                 : "=r"(r0), "=r"(r1), "=r"(r2), "=r"(r3) : "r"(a));
}
__device__ __forceinline__ void mma16816(float& c0, float& c1, float& c2, float& c3,
                                         unsigned a0, unsigned a1, unsigned a2, unsigned a3,
                                         unsigned b0, unsigned b1) {
    asm volatile(
        "mma.sync.aligned.m16n8k16.row.col.f32.f16.f16.f32 "
        "{%0,%1,%2,%3}, {%4,%5,%6,%7}, {%8,%9}, {%0,%1,%2,%3};"
        : "+f"(c0), "+f"(c1), "+f"(c2), "+f"(c3)
        : "r"(a0), "r"(a1), "r"(a2), "r"(a3), "r"(b0), "r"(b1));
}
__device__ __forceinline__ void cp_async16(unsigned saddr, const void* g) {
    asm volatile("cp.async.cg.shared.global [%0], [%1], 16;" :: "r"(saddr), "l"(g));
}
__device__ __forceinline__ void cp_commit() {
    asm volatile("cp.async.commit_group;");
}
template <int N> __device__ __forceinline__ void cp_wait() {
    asm volatile("cp.async.wait_group %0;" :: "n"(N));
}
__device__ __forceinline__ unsigned hmul2u(unsigned a, __half2 s) {
    __half2 r = __hmul2(*(__half2*)&a, s);
    return *(unsigned*)&r;
}

// ---------------------------------------------------------------------------
// K0: warp per row. cw1/qw2 fp32 dots (xlog2e); fp16: c plain, q*w3*log2e,
// q*qmf.
// ---------------------------------------------------------------------------
__global__ __launch_bounds__(256) void k0_prep(const float* __restrict__ c_rep,
                                               const float* __restrict__ q_rep,
                                               const int* __restrict__ q_mask,
                                               const float* __restrict__ w) {
    int gw   = (blockIdx.x * 256 + threadIdx.x) >> 5;
    int lane = threadIdx.x & 31;
    const int NC = BB * LCC;
    if (gw < NC) {
        float4 cv = *(const float4*)(c_rep + (size_t)gw * DDIM + lane * 4);
        float4 w1 = *(const float4*)(w + lane * 4);
        float s = cv.x * w1.x + cv.y * w1.y + cv.z * w1.z + cv.w * w1.w;
#pragma unroll
        for (int o = 16; o > 0; o >>= 1) s += __shfl_xor_sync(~0u, s, o);
        if (lane == 0) g_cw1[gw] = s * LOG2E;
        __half2 a0 = __floats2half2_rn(cv.x, cv.y);
        __half2 a1 = __floats2half2_rn(cv.z, cv.w);
        uint2 u; u.x = *(unsigned*)&a0; u.y = *(unsigned*)&a1;
        *(uint2*)(g_ch + (size_t)gw * DDIM + lane * 4) = u;
    } else if (gw < NC + BB * LQQ) {
        int r = gw - NC;
        float4 qv = *(const float4*)(q_rep + (size_t)r * DDIM + lane * 4);
        float4 w2 = *(const float4*)(w + DDIM + lane * 4);
        float4 w3 = *(const float4*)(w + 2 * DDIM + lane * 4);
        float s = qv.x * w2.x + qv.y * w2.y + qv.z * w2.z + qv.w * w2.w;
#pragma unroll
        for (int o = 16; o > 0; o >>= 1) s += __shfl_xor_sync(~0u, s, o);
        if (lane == 0) g_qw2[r] = s * LOG2E;
        __half2 a0 = __floats2half2_rn(qv.x * w3.x * LOG2E, qv.y * w3.y * LOG2E);
        __half2 a1 = __floats2half2_rn(qv.z * w3.z * LOG2E, qv.w * w3.w * LOG2E);
        uint2 u; u.x = *(unsigned*)&a0; u.y = *(unsigned*)&a1;
        *(uint2*)(g_qwh + (size_t)r * DDIM + lane * 4) = u;
        float mf = q_mask[r] ? 0.f : 1.f;
        __half2 m0 = __floats2half2_rn(qv.x * mf, qv.y * mf);
        __half2 m1 = __floats2half2_rn(qv.z * mf, qv.w * mf);
        uint2 v; v.x = *(unsigned*)&m0; v.y = *(unsigned*)&m1;
        *(uint2*)(g_qmh + (size_t)r * DDIM + lane * 4) = v;
    }
}

// ---------------------------------------------------------------------------
// K2: S' = cw1' + qw2' + c·(q*w3*L2E)^T  (log2 domain), E = 2^S' via
// ex2.approx.f16x2. z1inv finalized, z2 partials staged.
// ---------------------------------------------------------------------------
__global__ __launch_bounds__(256) void k2_SE(const int* __restrict__ c_mask,
                                             const int* __restrict__ q_mask) {
    int b = blockIdx.y, i0 = blockIdx.x * 128;
    extern __shared__ __half sm2[];
    __half* cw_s = sm2;                // [128][LDH]  A: rows i, cols d
    __half* q_s  = sm2 + 128 * LDH;    // [128][LDH]  B: rows j, cols d
    __shared__ float z1s[128][2];
    __shared__ float z2s[128][4];
    __shared__ float qmf_s[128], cmf_s[128];
    __shared__ float cw1_s[128], qw2_s[128];
    int t = threadIdx.x, lane = t & 31, wp = t >> 5, wm = wp >> 1, wn = wp & 1;
    if (t < 128) {
        qmf_s[t] = q_mask[b * LQQ + t] ? 0.f : 1.f;
        cmf_s[t] = c_mask[b * LCC + i0 + t] ? 0.f : 1.f;
        cw1_s[t] = g_cw1[b * LCC + i0 + t];
        qw2_s[t] = g_qw2[b * LQQ + t];
    }
    const uint4* gc = (const uint4*)(g_ch + ((size_t)(b * LCC + i0)) * DDIM);
    const uint4* gq = (const uint4*)(g_qwh + (size_t)b * LQQ * DDIM);
#pragma unroll
    for (int l = 0; l < 8; l++) {
        int u = t + l * 256, row = u >> 4, c16 = u & 15;
        *(uint4*)&cw_s[row * LDH + c16 * 8] = gc[u];
        *(uint4*)&q_s [row * LDH + c16 * 8] = gq[u];
    }
    __syncthreads();

    float acc[2][8][4];
#pragma unroll
    for (int a = 0; a < 2; a++)
#pragma unroll
        for (int c = 0; c < 8; c++)
#pragma unroll
            for (int k = 0; k < 4; k++) acc[a][c][k] = 0.f;

    unsigned aB = sm_addr(&cw_s[(wm * 32 + (lane & 15)) * LDH + 8 * (lane >> 4)]);
    unsigned bB = sm_addr(&q_s[(wn * 64 + 8 * ((lane >> 4) & 1) + (lane & 7)) * LDH
                               + 8 * ((lane >> 3) & 1)]);
#pragma unroll
    for (int ks = 0; ks < 8; ks++) {
        unsigned A[2][4];
        ldsm_x4(aB + ks * 32,                 A[0][0], A[0][1], A[0][2], A[0][3]);
        ldsm_x4(aB + 16 * LDH * 2 + ks * 32,  A[1][0], A[1][1], A[1][2], A[1][3]);
        unsigned Bf[8][2];
#pragma unroll
        for (int np = 0; np < 4; np++) {
            unsigned r0, r1, r2, r3;
            ldsm_x4(bB + np * (16 * LDH * 2) + ks * 32, r0, r1, r2, r3);
            Bf[2 * np][0] = r0; Bf[2 * np][1] = r1;
            Bf[2 * np + 1][0] = r2; Bf[2 * np + 1][1] = r3;
        }
#pragma unroll
        for (int a = 0; a < 2; a++)
#pragma unroll
            for (int c = 0; c < 8; c++)
                mma16816(acc[a][c][0], acc[a][c][1], acc[a][c][2], acc[a][c][3],
                         A[a][0], A[a][1], A[a][2], A[a][3], Bf[c][0], Bf[c][1]);
    }

    // epilogue: add rank-1 terms (log2 domain), ex2.f16x2, store E, z1/z2
    int g = lane >> 2, q4 = lane & 3;
    float z1a[2][2] = {{0.f, 0.f}, {0.f, 0.f}};
    float z2a[8][2];
#pragma unroll
    for (int c = 0; c < 8; c++) { z2a[c][0] = 0.f; z2a[c][1] = 0.f; }
#pragma unroll
    for (int a = 0; a < 2; a++) {
        int lr0 = wm * 32 + a * 16 + g;
        float cwv0 = cw1_s[lr0], cwv1 = cw1_s[lr0 + 8];
        float cmf0 = cmf_s[lr0], cmf1 = cmf_s[lr0 + 8];
        __half* e0p = g_Eh + ((size_t)(b * LCC + i0 + lr0)) * LQQ;
        __half* e1p = e0p + 8 * LQQ;
#pragma unroll
        for (int c = 0; c < 8; c++) {
            int col = wn * 64 + c * 8 + 2 * q4;
            float qw0 = qw2_s[col], qw1 = qw2_s[col + 1];
            float qf0 = qmf_s[col], qf1 = qmf_s[col + 1];
            __half2 p01 = __floats2half2_rn(acc[a][c][0] + cwv0 + qw0,
                                            acc[a][c][1] + cwv0 + qw1);
            __half2 p23 = __floats2half2_rn(acc[a][c][2] + cwv1 + qw0,
                                            acc[a][c][3] + cwv1 + qw1);
            __half2 e01 = h2exp2(p01);
            __half2 e23 = h2exp2(p23);
            *(__half2*)(e0p + col) = e01;
            *(__half2*)(e1p + col) = e23;
            float2 f01 = __half22float2(e01);
            float2 f23 = __half22float2(e23);
            z1a[a][0] += qf0 * f01.x + qf1 * f01.y;
            z1a[a][1] += qf0 * f23.x + qf1 * f23.y;
            z2a[c][0] += cmf0 * f01.x + cmf1 * f23.x;
            z2a[c][1] += cmf0 * f01.y + cmf1 * f23.y;
        }
    }
#pragma unroll
    for (int a = 0; a < 2; a++)
#pragma unroll
        for (int h = 0; h < 2; h++) {
            float v = z1a[a][h];
            v += __shfl_xor_sync(~0u, v, 1);
            v += __shfl_xor_sync(~0u, v, 2);
            if (q4 == 0) z1s[wm * 32 + a * 16 + g + 8 * h][wn] = v;
        }
#pragma unroll
    for (int c = 0; c < 8; c++)
#pragma unroll
        for (int s = 0; s < 2; s++) {
            float v = z2a[c][s];
            v += __shfl_xor_sync(~0u, v, 4);
            v += __shfl_xor_sync(~0u, v, 8);
            v += __shfl_xor_sync(~0u, v, 16);
            if (g == 0) z2s[wn * 64 + c * 8 + 2 * q4 + s][wm] = v;
        }
    __syncthreads();
    if (t < 128) {
        g_z1inv[b * LCC + i0 + t] = 1.f / (z1s[t][0] + z1s[t][1]);
        g_z2p[blockIdx.x][b * LQQ + t] = z2s[t][0] + z2s[t][1] + z2s[t][2] + z2s[t][3];
    }
}

// ---------------------------------------------------------------------------
// K3: T[j,d] = qmf[j]/z2[j] * sum_i cmf[i]*E[i,j]*c[i,d]  -> fp16 g_Tm
// N-split over d halves: grid (2, BB). M=128 j, N=64 d, K=1024 i.
// ---------------------------------------------------------------------------
#define EBUFB (64 * LDH * 2)    // bytes per E buffer
#define CBUFB (64 * LDHC * 2)   // bytes per c buffer
__global__ __launch_bounds__(256) void k3_T(const int* __restrict__ c_mask,
                                            const int* __restrict__ q_mask) {
    int b = blockIdx.y, d0 = blockIdx.x * 64;
    extern __shared__ __half s3[];
    __half* E_s   = s3;                         // 2 x 64 x LDH
    __half* c_s   = s3 + 2 * 64 * LDH;          // 2 x 64 x LDHC
    __half* cmf_s = s3 + 2 * 64 * LDH + 2 * 64 * LDHC;  // 1024
    float*  f_s   = (float*)(cmf_s + 1024);     // 128
    int t = threadIdx.x, lane = t & 31, wp = t >> 5, wm = wp >> 1, wn = wp & 1;

    unsigned Ebase = sm_addr(E_s);
    unsigned Cbase = sm_addr(c_s);
    {
        const char* gE = (const char*)(g_Eh + ((size_t)b * LCC) * LQQ);
        const char* gC = (const char*)(g_ch + ((size_t)b * LCC) * DDIM + d0);
#pragma unroll
        for (int l = 0; l < 4; l++) {
            int u = t + l * 256, row = u >> 4, c16 = u & 15;
            cp_async16(Ebase + (row * LDH + c16 * 8) * 2, gE + ((size_t)row * LQQ + c16 * 8) * 2);
        }
#pragma unroll
        for (int l = 0; l < 2; l++) {
            int u = t + l * 256, row = u >> 3, c8 = u & 7;
            cp_async16(Cbase + (row * LDHC + c8 * 8) * 2, gC + ((size_t)row * DDIM + c8 * 8) * 2);
        }
        cp_commit();
    }
#pragma unroll
    for (int l = 0; l < 4; l++) {
        int i = t + l * 256;
        cmf_s[i] = __float2half(c_mask[b * LCC + i] ? 0.f : 1.f);
    }
    if (t < 128) {
        float z2 = 0.f;
#pragma unroll
        for (int s = 0; s < 8; s++) z2 += g_z2p[s][b * LQQ + t];
        f_s[t] = q_mask[b * LQQ + t] ? 0.f : (1.f / z2);
    }

    float acc[2][4][4];
#pragma unroll
    for (int a = 0; a < 2; a++)
#pragma unroll
        for (int c = 0; c < 4; c++)
#pragma unroll
            for (int k = 0; k < 4; k++) acc[a][c][k] = 0.f;

    unsigned aB = Ebase + (((lane & 7) + 8 * ((lane >> 4) & 1)) * LDH
                           + wm * 32 + 8 * ((lane >> 3) & 1)) * 2;
    unsigned bB = Cbase + (((lane & 7) + 8 * ((lane >> 3) & 1)) * LDHC
                           + wn * 32 + 8 * ((lane >> 4) & 1)) * 2;

    for (int kc = 0; kc < 16; kc++) {
        int buf = kc & 1;
        if (kc + 1 < 16) {
            int nxt = buf ^ 1;
            const char* gE = (const char*)(g_Eh + ((size_t)(b * LCC + (kc + 1) * 64)) * LQQ);
            const char* gC = (const char*)(g_ch + ((size_t)(b * LCC + (kc + 1) * 64)) * DDIM + d0);
#pragma unroll
            for (int l = 0; l < 4; l++) {
                int u = t + l * 256, row = u >> 4, c16 = u & 15;
                cp_async16(Ebase + nxt * EBUFB + (row * LDH + c16 * 8) * 2,
                           gE + ((size_t)row * LQQ + c16 * 8) * 2);
            }
#pragma unroll
            for (int l = 0; l < 2; l++) {
                int u = t + l * 256, row = u >> 3, c8 = u & 7;
                cp_async16(Cbase + nxt * CBUFB + (row * LDHC + c8 * 8) * 2,
                           gC + ((size_t)row * DDIM + c8 * 8) * 2);
            }
            cp_commit();
            cp_wait<1>();
        } else {
            cp_wait<0>();
        }
        __syncthreads();
#pragma unroll
        for (int ks = 0; ks < 4; ks++) {
            int ibase = kc * 64 + ks * 16;
            __half2 cm_lo = *(__half2*)&cmf_s[ibase + (lane & 3) * 2];
            __half2 cm_hi = *(__half2*)&cmf_s[ibase + 8 + (lane & 3) * 2];
            unsigned A[2][4];
            ldsm_x4t(aB + buf * EBUFB + ks * (16 * LDH * 2),      A[0][0], A[0][1], A[0][2], A[0][3]);
            ldsm_x4t(aB + buf * EBUFB + ks * (16 * LDH * 2) + 32, A[1][0], A[1][1], A[1][2], A[1][3]);
#pragma unroll
            for (int a = 0; a < 2; a++) {
                A[a][0] = hmul2u(A[a][0], cm_lo);
                A[a][1] = hmul2u(A[a][1], cm_lo);
                A[a][2] = hmul2u(A[a][2], cm_hi);
                A[a][3] = hmul2u(A[a][3], cm_hi);
            }
            unsigned Bf[4][2];
#pragma unroll
            for (int np = 0; np < 2; np++) {
                unsigned r0, r1, r2, r3;
                ldsm_x4t(bB + buf * CBUFB + ks * (16 * LDHC * 2) + np * 32, r0, r1, r2, r3);
                Bf[2 * np][0] = r0; Bf[2 * np][1] = r1;
                Bf[2 * np + 1][0] = r2; Bf[2 * np + 1][1] = r3;
            }
#pragma unroll
            for (int a = 0; a < 2; a++)
#pragma unroll
                for (int c = 0; c < 4; c++)
                    mma16816(acc[a][c][0], acc[a][c][1], acc[a][c][2], acc[a][c][3],
                             A[a][0], A[a][1], A[a][2], A[a][3], Bf[c][0], Bf[c][1]);
        }
        __syncthreads();
    }

    int g = lane >> 2, q4 = lane & 3;
#pragma unroll
    for (int a = 0; a < 2; a++) {
        int j0 = wm * 32 + a * 16 + g;
        float f0 = f_s[j0], f1 = f_s[j0 + 8];
        __half* o0 = g_Tm + ((size_t)(b * LQQ + j0)) * DDIM + d0;
        __half* o1 = o0 + 8 * DDIM;
#pragma unroll
        for (int c = 0; c < 4; c++) {
            int col = wn * 32 + c * 8 + 2 * q4;
            *(__half2*)(o0 + col) = __floats2half2_rn(acc[a][c][0] * f0, acc[a][c][1] * f0);
            *(__half2*)(o1 + col) = __floats2half2_rn(acc[a][c][2] * f1, acc[a][c][3] * f1);
        }
    }
}

// ---------------------------------------------------------------------------
// K4: fused dual GEMM A = (E·qmh)/z1, Batt = (E·Tm)/z1; parallel smem-staged
// epilogue, fully-coalesced float4 stores of [c, A, c*A, c*Batt].
// Grid (32, BB): bx&1 = d-half, bx>>1 = i-tile of 64. M=64 i, N=64 d, K=128 j.
// 3 CTAs/SM (reg cap 85) for latency hiding.
// ---------------------------------------------------------------------------
__global__ __launch_bounds__(256, 3) void k4_out(const float* __restrict__ c_rep,
                                                 float* __restrict__ out) {
    int b = blockIdx.y;
    int i0 = (blockIdx.x >> 1) * 64;
    int d0 = (blockIdx.x & 1) * 64;
    extern __shared__ __half sm4[];
    __half* E_s = sm4;                   // [64][LDH]    rows i, cols j (A)
    __half* q_s = sm4 + 64 * LDH;        // [128][LDHC]  rows j, d-half (B)
    __half* t_s = q_s + 128 * LDHC;      // [128][LDHC]  rows j, d-half (B)
    float* Asm = (float*)sm4;            // staging (reused post-MMA): [64][LDS4]
    float* Bsm = Asm + 64 * LDS4;
    int t = threadIdx.x, lane = t & 31, wp = t >> 5, wm = wp >> 1, wn = wp & 1;
    const uint4* gE = (const uint4*)(g_Eh + ((size_t)(b * LCC + i0)) * LQQ);
    const __half* gQ = g_qmh + (size_t)b * LQQ * DDIM + d0;
    const __half* gT = g_Tm + (size_t)b * LQQ * DDIM + d0;
#pragma unroll
    for (int l = 0; l < 4; l++) {
        int u = t + l * 256, row = u >> 4, c16 = u & 15;
        *(uint4*)&E_s[row * LDH + c16 * 8] = gE[u];
    }
#pragma unroll
    for (int l = 0; l < 4; l++) {
        int u = t + l * 256, row = u >> 3, c8 = u & 7;
        *(uint4*)&q_s[row * LDHC + c8 * 8] = *(const uint4*)(gQ + (size_t)row * DDIM + c8 * 8);
        *(uint4*)&t_s[row * LDHC + c8 * 8] = *(const uint4*)(gT + (size_t)row * DDIM + c8 * 8);
    }
    __syncthreads();

    float accA[4][4], accB[4][4];
#pragma unroll
    for (int c = 0; c < 4; c++)
#pragma unroll
        for (int k = 0; k < 4; k++) { accA[c][k] = 0.f; accB[c][k] = 0.f; }

    unsigned aB = sm_addr(&E_s[(wm * 16 + (lane & 15)) * LDH + 8 * (lane >> 4)]);
    unsigned qB = sm_addr(&q_s[((lane & 7) + 8 * ((lane >> 3) & 1)) * LDHC
                               + wn * 32 + 8 * ((lane >> 4) & 1)]);
    unsigned tB = sm_addr(&t_s[((lane & 7) + 8 * ((lane >> 3) & 1)) * LDHC
                               + wn * 32 + 8 * ((lane >> 4) & 1)]);
#pragma unroll
    for (int ks = 0; ks < 8; ks++) {
        unsigned A0, A1, A2, A3;
        ldsm_x4(aB + ks * 32, A0, A1, A2, A3);
#pragma unroll
        for (int np = 0; np < 2; np++) {
            unsigned r0, r1, r2, r3;
            ldsm_x4t(qB + ks * (16 * LDHC * 2) + np * 32, r0, r1, r2, r3);
            mma16816(accA[2 * np][0], accA[2 * np][1], accA[2 * np][2], accA[2 * np][3],
                     A0, A1, A2, A3, r0, r1);
            mma16816(accA[2 * np + 1][0], accA[2 * np + 1][1], accA[2 * np + 1][2], accA[2 * np + 1][3],
                     A0, A1, A2, A3, r2, r3);
            ldsm_x4t(tB + ks * (16 * LDHC * 2) + np * 32, r0, r1, r2, r3);
            mma16816(accB[2 * np][0], accB[2 * np][1], accB[2 * np][2], accB[2 * np][3],
                     A0, A1, A2, A3, r0, r1);
            mma16816(accB[2 * np + 1][0], accB[2 * np + 1][1], accB[2 * np + 1][2], accB[2 * np + 1][3],
                     A0, A1, A2, A3, r2, r3);
        }
    }

    int g = lane >> 2, q4 = lane & 3;
    float z0, z1v;
    {
        size_t gr = (size_t)(b * LCC + i0 + wm * 16 + g);
        z0 = g_z1inv[gr];
        z1v = g_z1inv[gr + 8];
    }
    __syncthreads();   // all warps done reading E_s/q_s/t_s; smem reused below

    // all-warp parallel staging of 64 rows
    {
        int r0 = wm * 16 + g, r1 = r0 + 8;
#pragma unroll
        for (int c = 0; c < 4; c++) {
            int col = wn * 32 + c * 8 + 2 * q4;
            *(float2*)&Asm[r0 * LDS4 + col] = make_float2(accA[c][0] * z0, accA[c][1] * z0);
            *(float2*)&Asm[r1 * LDS4 + col] = make_float2(accA[c][2] * z1v, accA[c][3] * z1v);
            *(float2*)&Bsm[r0 * LDS4 + col] = make_float2(accB[c][0] * z0, accB[c][1] * z0);
            *(float2*)&Bsm[r1 * LDS4 + col] = make_float2(accB[c][2] * z1v, accB[c][3] * z1v);
        }
    }
    __syncthreads();

    // dense float4 stores: 64 rows x 64 cols, 4 iterations
#pragma unroll
    for (int it = 0; it < 4; it++) {
        int u = t + it * 256;
        int row = u >> 4, col = (u & 15) * 4;
        size_t gr = (size_t)(b * LCC + i0 + row);
        float4 c4 = *(const float4*)(c_rep + gr * DDIM + d0 + col);
        float4 a4 = *(const float4*)&Asm[row * LDS4 + col];
        float4 b4 = *(const float4*)&Bsm[row * LDS4 + col];
        float* ob = out + gr * (4 * DDIM) + d0 + col;
        *(float4*)ob = c4;
        *(float4*)(ob + DDIM) = a4;
        *(float4*)(ob + 2 * DDIM) = make_float4(c4.x * a4.x, c4.y * a4.y, c4.z * a4.z, c4.w * a4.w);
        *(float4*)(ob + 3 * DDIM) = make_float4(c4.x * b4.x, c4.y * b4.y, c4.z * b4.z, c4.w * b4.w);
    }
}

// ---------------------------------------------------------------------------
extern "C" void kernel_launch(void* const* d_in, const int* in_sizes, int n_in,
                              void* d_out, int out_size) {
    const float* c_rep  = (const float*)d_in[0];
    const float* q_rep  = (const float*)d_in[1];
    const int*   c_mask = (const int*)d_in[2];
    const int*   q_mask = (const int*)d_in[3];
    const float* w      = (const float*)d_in[4];
    float* out = (float*)d_out;

    k0_prep<<<(BB * LCC + BB * LQQ) / 8, 256>>>(c_rep, q_rep, q_mask, w);
    {
        int smem = 2 * 128 * LDH * 2;  // 69632
        cudaFuncSetAttribute(k2_SE, cudaFuncAttributeMaxDynamicSharedMemorySize, smem);
        dim3 gr(8, BB);
        k2_SE<<<gr, 256, smem>>>(c_mask, q_mask);
    }
    {
        int smem = 2 * EBUFB + 2 * CBUFB + 1024 * 2 + 128 * 4;  // 55808
        cudaFuncSetAttribute(k3_T, cudaFuncAttributeMaxDynamicSharedMemorySize, smem);
        dim3 gr(2, BB);
        k3_T<<<gr, 256, smem>>>(c_mask, q_mask);
    }
    {
        int smem = (64 * LDH + 2 * 128 * LDHC) * 2;  // 54272 (>= staging 36864)
        cudaFuncSetAttribute(k4_out, cudaFuncAttributeMaxDynamicSharedMemorySize, smem);
        dim3 gr(32, BB);
        k4_out<<<gr, 256, smem>>>(c_rep, out);
    }
}